// round 2
// baseline (speedup 1.0000x reference)
#include <cuda_runtime.h>
#include <cuda_bf16.h>

#define NN      50000
#define EE      800000
#define ET      850000
#define HID     128
#define HEADS   4
#define DH      32
#define NB      64
#define LAYERS  3
#define LN_EPS  1e-5f
#define NEG_SLOPE 0.2f

// ---------------- device scratch ----------------
__device__ float g_h[NN * HID];
__device__ float g_tmp[NN * HID];
__device__ float g_as[NN * HEADS];
__device__ float g_ad[NN * HEADS];
__device__ int   g_deg[NN];
__device__ int   g_off[NN + 1];
__device__ int   g_cur[NN];
__device__ int   g_csr_src[ET];

// ---------------- helpers ----------------
__device__ __forceinline__ float warpSum(float v) {
#pragma unroll
    for (int o = 16; o > 0; o >>= 1) v += __shfl_xor_sync(0xffffffffu, v, o);
    return v;
}
__device__ __forceinline__ float lrelu(float x) { return x > 0.f ? x : NEG_SLOPE * x; }
__device__ __forceinline__ float silu(float x) { return x / (1.f + __expf(-x)); }

__device__ __forceinline__ unsigned tf32_cvt(float a) {
    unsigned r;
    asm("cvt.rna.tf32.f32 %0, %1;" : "=r"(r) : "f"(a));
    return r;
}
__device__ __forceinline__ void mma_tf32(float* c, const unsigned* a, const unsigned* b) {
    asm("mma.sync.aligned.m16n8k8.row.col.f32.tf32.tf32.f32 "
        "{%0,%1,%2,%3},{%4,%5,%6,%7},{%8,%9},{%0,%1,%2,%3};"
        : "+f"(c[0]), "+f"(c[1]), "+f"(c[2]), "+f"(c[3])
        : "r"(a[0]), "r"(a[1]), "r"(a[2]), "r"(a[3]), "r"(b[0]), "r"(b[1]));
}

// ---------------- CSR build ----------------
__global__ void zero_deg_kernel(int* deg) {
    int i = blockIdx.x * blockDim.x + threadIdx.x;
    if (i < NN) deg[i] = 0;
}
__global__ void count_deg_kernel(const int* __restrict__ ei, int* __restrict__ deg) {
    int i = blockIdx.x * blockDim.x + threadIdx.x;
    if (i >= ET) return;
    int dst = (i < EE) ? ei[EE + i] : (i - EE);
    atomicAdd(&deg[dst], 1);
}
__global__ void scan_kernel(const int* __restrict__ deg, int* __restrict__ off) {
    __shared__ int wsum[32];
    __shared__ int carry;
    int tid = threadIdx.x, lane = tid & 31, w = tid >> 5;
    if (tid == 0) carry = 0;
    __syncthreads();
    for (int base = 0; base < NN; base += 1024) {
        int i = base + tid;
        int v = (i < NN) ? deg[i] : 0;
        int x = v;
#pragma unroll
        for (int o = 1; o < 32; o <<= 1) {
            int t = __shfl_up_sync(0xffffffffu, x, o);
            if (lane >= o) x += t;
        }
        if (lane == 31) wsum[w] = x;
        __syncthreads();
        if (w == 0) {
            int s = wsum[lane];
#pragma unroll
            for (int o = 1; o < 32; o <<= 1) {
                int t = __shfl_up_sync(0xffffffffu, s, o);
                if (lane >= o) s += t;
            }
            wsum[lane] = s;
        }
        __syncthreads();
        int excl = x - v + (w ? wsum[w - 1] : 0) + carry;
        if (i < NN) off[i] = excl;
        __syncthreads();
        if (tid == 0) carry += wsum[31];
        __syncthreads();
    }
    if (threadIdx.x == 0) off[NN] = carry;
}
__global__ void copy_cursor_kernel(const int* __restrict__ off, int* __restrict__ cur) {
    int i = blockIdx.x * blockDim.x + threadIdx.x;
    if (i < NN) cur[i] = off[i];
}
__global__ void scatter_kernel(const int* __restrict__ ei, int* __restrict__ cur,
                               int* __restrict__ csr_src) {
    int i = blockIdx.x * blockDim.x + threadIdx.x;
    if (i >= ET) return;
    int src, dst;
    if (i < EE) { src = ei[i]; dst = ei[EE + i]; }
    else        { src = i - EE; dst = i - EE; }
    int pos = atomicAdd(&cur[dst], 1);
    csr_src[pos] = src;
}

// ---------------- TF32 tensor-core GEMM: C[M,128] = A[M,128] @ W[128,128] ---
// 3xTF32 split for fp32-class accuracy. Block = 128 rows x 128 cols, K chunked
// at 64. 256 threads = 8 warps in a 4x2 (m x n) grid; warp tile 32x64.
#define GSTR 68   // smem k-stride (pad): bank = (row*4 + col) % 32, conflict-free
__global__ __launch_bounds__(256, 1)
void gemm_tf32_kernel(const float* __restrict__ A, const float* __restrict__ W,
                      float* __restrict__ C, int M) {
    extern __shared__ float smem[];
    float* sAh = smem;                 // [128][GSTR]
    float* sAl = sAh + 128 * GSTR;
    float* sBh = sAl + 128 * GSTR;     // [n][k] layout (B transposed)
    float* sBl = sBh + 128 * GSTR;
    const unsigned* uAh = (const unsigned*)sAh;
    const unsigned* uAl = (const unsigned*)sAl;
    const unsigned* uBh = (const unsigned*)sBh;
    const unsigned* uBl = (const unsigned*)sBl;

    const int tid = threadIdx.x;
    const int wid = tid >> 5, lane = tid & 31;
    const int g = lane >> 2, tig = lane & 3;
    const int rm = (wid >> 1) * 32;    // warp row base
    const int cn = (wid & 1) * 64;     // warp col base
    const int row0 = blockIdx.x * 128;

    float acc[2][8][4];
#pragma unroll
    for (int i = 0; i < 2; i++)
#pragma unroll
        for (int j = 0; j < 8; j++)
#pragma unroll
            for (int k = 0; k < 4; k++) acc[i][j][k] = 0.f;

    for (int ch = 0; ch < 2; ch++) {
        const int kc = ch * 64;
        // load A chunk: 128 rows x 64 cols = 2048 float4, 8 per thread
#pragma unroll
        for (int i = 0; i < 8; i++) {
            int s = tid + i * 256;
            int r = s >> 4;
            int col = (s & 15) << 2;
            int gr = row0 + r;
            float4 v = make_float4(0.f, 0.f, 0.f, 0.f);
            if (gr < M) v = *(const float4*)(A + (long)gr * 128 + kc + col);
            float hx = __uint_as_float(tf32_cvt(v.x));
            float hy = __uint_as_float(tf32_cvt(v.y));
            float hz = __uint_as_float(tf32_cvt(v.z));
            float hw = __uint_as_float(tf32_cvt(v.w));
            float* ah = sAh + r * GSTR + col;
            float* al = sAl + r * GSTR + col;
            ah[0] = hx; ah[1] = hy; ah[2] = hz; ah[3] = hw;
            al[0] = __uint_as_float(tf32_cvt(v.x - hx));
            al[1] = __uint_as_float(tf32_cvt(v.y - hy));
            al[2] = __uint_as_float(tf32_cvt(v.z - hz));
            al[3] = __uint_as_float(tf32_cvt(v.w - hw));
        }
        // load B chunk: 64 k-rows x 128 cols, store transposed [n][k]
#pragma unroll
        for (int i = 0; i < 8; i++) {
            int s = tid + i * 256;
            int k = s >> 5;
            int n = (s & 31) << 2;
            float4 v = *(const float4*)(W + (long)(kc + k) * 128 + n);
            float h0 = __uint_as_float(tf32_cvt(v.x));
            float h1 = __uint_as_float(tf32_cvt(v.y));
            float h2 = __uint_as_float(tf32_cvt(v.z));
            float h3 = __uint_as_float(tf32_cvt(v.w));
            sBh[(n + 0) * GSTR + k] = h0;
            sBh[(n + 1) * GSTR + k] = h1;
            sBh[(n + 2) * GSTR + k] = h2;
            sBh[(n + 3) * GSTR + k] = h3;
            sBl[(n + 0) * GSTR + k] = __uint_as_float(tf32_cvt(v.x - h0));
            sBl[(n + 1) * GSTR + k] = __uint_as_float(tf32_cvt(v.y - h1));
            sBl[(n + 2) * GSTR + k] = __uint_as_float(tf32_cvt(v.z - h2));
            sBl[(n + 3) * GSTR + k] = __uint_as_float(tf32_cvt(v.w - h3));
        }
        __syncthreads();

#pragma unroll
        for (int ks = 0; ks < 8; ks++) {
            const int kk = ks * 8;
            unsigned ah[2][4], al[2][4], bh[8][2], bl[8][2];
#pragma unroll
            for (int mf = 0; mf < 2; mf++) {
                int r = rm + mf * 16 + g;
                ah[mf][0] = uAh[r * GSTR + kk + tig];
                ah[mf][1] = uAh[(r + 8) * GSTR + kk + tig];
                ah[mf][2] = uAh[r * GSTR + kk + tig + 4];
                ah[mf][3] = uAh[(r + 8) * GSTR + kk + tig + 4];
                al[mf][0] = uAl[r * GSTR + kk + tig];
                al[mf][1] = uAl[(r + 8) * GSTR + kk + tig];
                al[mf][2] = uAl[r * GSTR + kk + tig + 4];
                al[mf][3] = uAl[(r + 8) * GSTR + kk + tig + 4];
            }
#pragma unroll
            for (int nf = 0; nf < 8; nf++) {
                int c = cn + nf * 8 + g;
                bh[nf][0] = uBh[c * GSTR + kk + tig];
                bh[nf][1] = uBh[c * GSTR + kk + tig + 4];
                bl[nf][0] = uBl[c * GSTR + kk + tig];
                bl[nf][1] = uBl[c * GSTR + kk + tig + 4];
            }
#pragma unroll
            for (int mf = 0; mf < 2; mf++)
#pragma unroll
                for (int nf = 0; nf < 8; nf++) {
                    mma_tf32(acc[mf][nf], al[mf], bh[nf]);
                    mma_tf32(acc[mf][nf], ah[mf], bl[nf]);
                    mma_tf32(acc[mf][nf], ah[mf], bh[nf]);
                }
        }
        __syncthreads();
    }

    // epilogue
#pragma unroll
    for (int mf = 0; mf < 2; mf++) {
        int r = row0 + rm + mf * 16 + g;
#pragma unroll
        for (int nf = 0; nf < 8; nf++) {
            int c = cn + nf * 8 + tig * 2;
            if (r < M) {
                float2 v = make_float2(acc[mf][nf][0], acc[mf][nf][1]);
                *(float2*)(C + (long)r * 128 + c) = v;
            }
            if (r + 8 < M) {
                float2 v = make_float2(acc[mf][nf][2], acc[mf][nf][3]);
                *(float2*)(C + (long)(r + 8) * 128 + c) = v;
            }
        }
    }
}

// ---------------- encoder LN + SiLU (warp per node) ----------------
__global__ void ln_silu_kernel(const float* __restrict__ in, const float* __restrict__ bias,
                               const float* __restrict__ g, const float* __restrict__ be,
                               float* __restrict__ out) {
    int warp = (blockIdx.x * blockDim.x + threadIdx.x) >> 5;
    if (warp >= NN) return;
    int lane = threadIdx.x & 31;
    int col  = lane * 4;
    float4 v  = *(const float4*)(in + (long)warp * 128 + col);
    float4 b4 = *(const float4*)(bias + col);
    v.x += b4.x; v.y += b4.y; v.z += b4.z; v.w += b4.w;
    float mu = warpSum(v.x + v.y + v.z + v.w) * (1.f / 128.f);
    float dx = v.x - mu, dy = v.y - mu, dz = v.z - mu, dw = v.w - mu;
    float var = warpSum(dx * dx + dy * dy + dz * dz + dw * dw) * (1.f / 128.f);
    float r = rsqrtf(var + LN_EPS);
    float4 gv  = *(const float4*)(g + col);
    float4 bev = *(const float4*)(be + col);
    float y;
    y = dx * r * gv.x + bev.x; v.x = silu(y);
    y = dy * r * gv.y + bev.y; v.y = silu(y);
    y = dz * r * gv.z + bev.z; v.z = silu(y);
    y = dw * r * gv.w + bev.w; v.w = silu(y);
    *(float4*)(out + (long)warp * 128 + col) = v;
}

// ---------------- per-node attention logits ----------------
__global__ void attn_prep_kernel(const float* __restrict__ hh, const float* __restrict__ ws,
                                 const float* __restrict__ wd, float* __restrict__ a_s,
                                 float* __restrict__ a_d) {
    int idx = blockIdx.x * blockDim.x + threadIdx.x;
    if (idx >= NN * HEADS) return;
    int n = idx >> 2, hd = idx & 3;
    const float* row = hh + (long)n * 128 + hd * 32;
    const float* s1  = ws + hd * 32;
    const float* s2  = wd + hd * 32;
    float u = 0.f, t = 0.f;
#pragma unroll
    for (int d = 0; d < 32; d += 4) {
        float4 v  = *(const float4*)(row + d);
        float4 w1 = *(const float4*)(s1 + d);
        float4 w2 = *(const float4*)(s2 + d);
        u += v.x * w1.x + v.y * w1.y + v.z * w1.z + v.w * w1.w;
        t += v.x * w2.x + v.y * w2.y + v.z * w2.z + v.w * w2.w;
    }
    a_s[idx] = u;
    a_d[idx] = t;
}

// -------- GAT aggregate (online softmax) + LN + SiLU + residual -----------
__global__ void gat_aggregate_kernel(const float* __restrict__ hh, const float* __restrict__ a_s,
                                     const float* __restrict__ a_d, const int* __restrict__ off,
                                     const int* __restrict__ csr_src, const float* __restrict__ bg,
                                     const float* __restrict__ gg, const float* __restrict__ bgg,
                                     float* __restrict__ h) {
    int n = (blockIdx.x * blockDim.x + threadIdx.x) >> 5;
    if (n >= NN) return;
    int lane = threadIdx.x & 31;
    int beg = off[n], end = off[n + 1];

    float4 adv = *(const float4*)(a_d + n * 4);
    float m0 = -1e30f, m1 = -1e30f, m2 = -1e30f, m3 = -1e30f;
    float s0 = 0.f, s1 = 0.f, s2 = 0.f, s3 = 0.f;
    // pass 1: online max+sumexp per head
    for (int j = beg + lane; j < end; j += 32) {
        int s = csr_src[j];
        float4 asv = *(const float4*)(a_s + s * 4);
        float e;
        e = lrelu(asv.x + adv.x);
        if (e > m0) { s0 = s0 * __expf(m0 - e) + 1.f; m0 = e; } else s0 += __expf(e - m0);
        e = lrelu(asv.y + adv.y);
        if (e > m1) { s1 = s1 * __expf(m1 - e) + 1.f; m1 = e; } else s1 += __expf(e - m1);
        e = lrelu(asv.z + adv.z);
        if (e > m2) { s2 = s2 * __expf(m2 - e) + 1.f; m2 = e; } else s2 += __expf(e - m2);
        e = lrelu(asv.w + adv.w);
        if (e > m3) { s3 = s3 * __expf(m3 - e) + 1.f; m3 = e; } else s3 += __expf(e - m3);
    }
#pragma unroll
    for (int o = 16; o > 0; o >>= 1) {
        float om, os, nm;
        om = __shfl_xor_sync(0xffffffffu, m0, o); os = __shfl_xor_sync(0xffffffffu, s0, o);
        nm = fmaxf(m0, om); s0 = s0 * __expf(m0 - nm) + os * __expf(om - nm); m0 = nm;
        om = __shfl_xor_sync(0xffffffffu, m1, o); os = __shfl_xor_sync(0xffffffffu, s1, o);
        nm = fmaxf(m1, om); s1 = s1 * __expf(m1 - nm) + os * __expf(om - nm); m1 = nm;
        om = __shfl_xor_sync(0xffffffffu, m2, o); os = __shfl_xor_sync(0xffffffffu, s2, o);
        nm = fmaxf(m2, om); s2 = s2 * __expf(m2 - nm) + os * __expf(om - nm); m2 = nm;
        om = __shfl_xor_sync(0xffffffffu, m3, o); os = __shfl_xor_sync(0xffffffffu, s3, o);
        nm = fmaxf(m3, om); s3 = s3 * __expf(m3 - nm) + os * __expf(om - nm); m3 = nm;
    }

    int hd = lane >> 3;
    float mh   = (hd == 0) ? m0 : (hd == 1) ? m1 : (hd == 2) ? m2 : m3;
    float adh  = (hd == 0) ? adv.x : (hd == 1) ? adv.y : (hd == 2) ? adv.z : adv.w;
    float invh = 1.f / ((hd == 0) ? s0 : (hd == 1) ? s1 : (hd == 2) ? s2 : s3);

    const int col = lane * 4;
    float4 acc = make_float4(0.f, 0.f, 0.f, 0.f);
    // pass 2: weighted accumulate of hh[src]
    for (int j = beg; j < end; j++) {
        int s = csr_src[j];
        float w = __expf(lrelu(a_s[s * 4 + hd] + adh) - mh) * invh;
        float4 v = *(const float4*)(hh + (long)s * 128 + col);
        acc.x += v.x * w; acc.y += v.y * w; acc.z += v.z * w; acc.w += v.w * w;
    }
    // + bg, LayerNorm, SiLU, + residual
    float4 bgv = *(const float4*)(bg + col);
    acc.x += bgv.x; acc.y += bgv.y; acc.z += bgv.z; acc.w += bgv.w;
    float mu = warpSum(acc.x + acc.y + acc.z + acc.w) * (1.f / 128.f);
    float dx = acc.x - mu, dy = acc.y - mu, dz = acc.z - mu, dw = acc.w - mu;
    float var = warpSum(dx * dx + dy * dy + dz * dz + dw * dw) * (1.f / 128.f);
    float r = rsqrtf(var + LN_EPS);
    float4 gv  = *(const float4*)(gg + col);
    float4 bv  = *(const float4*)(bgg + col);
    float4 old = *(const float4*)(h + (long)n * 128 + col);
    float y;
    y = dx * r * gv.x + bv.x; acc.x = silu(y) + old.x;
    y = dy * r * gv.y + bv.y; acc.y = silu(y) + old.y;
    y = dz * r * gv.z + bv.z; acc.z = silu(y) + old.z;
    y = dw * r * gv.w + bv.w; acc.w = silu(y) + old.w;
    *(float4*)(h + (long)n * 128 + col) = acc;
}

// -------- fused pool (sorted batch) + projection + LN + SiLU ------------
__global__ void pool_final_kernel(const float* __restrict__ h, const int* __restrict__ batch,
                                  const float* __restrict__ Wp, const float* __restrict__ bp,
                                  const float* __restrict__ gp, const float* __restrict__ bep,
                                  float* __restrict__ out) {
    __shared__ float p[128];
    __shared__ float sh[4];
    __shared__ int bounds[2];
    int b = blockIdx.x, t = threadIdx.x;
    int lane = t & 31, w = t >> 5;
    if (t < 2) {
        int target = b + t;
        int lo = 0, hi = NN;
        while (lo < hi) {
            int mid = (lo + hi) >> 1;
            if (batch[mid] < target) lo = mid + 1; else hi = mid;
        }
        bounds[t] = lo;
    }
    __syncthreads();
    int lo = bounds[0], hi = bounds[1];
    float s = 0.f;
#pragma unroll 4
    for (int n = lo; n < hi; n++) s += h[(long)n * 128 + t];
    float c = (float)(hi - lo > 0 ? hi - lo : 1);
    p[t] = s / c;
    __syncthreads();
    float acc = bp[t];
#pragma unroll 8
    for (int k = 0; k < 128; k++) acc += p[k] * Wp[k * 128 + t];
    float v = warpSum(acc);
    if (lane == 0) sh[w] = v;
    __syncthreads();
    float mu = (sh[0] + sh[1] + sh[2] + sh[3]) * (1.f / 128.f);
    __syncthreads();
    float d = acc - mu;
    v = warpSum(d * d);
    if (lane == 0) sh[w] = v;
    __syncthreads();
    float var = (sh[0] + sh[1] + sh[2] + sh[3]) * (1.f / 128.f);
    float r = rsqrtf(var + LN_EPS);
    float y = d * r * gp[t] + bep[t];
    out[b * 128 + t] = silu(y);
}

// ---------------- launch ----------------
extern "C" void kernel_launch(void* const* d_in, const int* in_sizes, int n_in,
                              void* d_out, int out_size) {
    const float* x       = (const float*)d_in[0];
    const int*   ei      = (const int*)d_in[1];
    const int*   batch   = (const int*)d_in[2];
    const float* W0      = (const float*)d_in[3];
    const float* b0      = (const float*)d_in[4];
    const float* g0      = (const float*)d_in[5];
    const float* be0     = (const float*)d_in[6];
    const float* Wg      = (const float*)d_in[7];
    const float* att_src = (const float*)d_in[8];
    const float* att_dst = (const float*)d_in[9];
    const float* bg      = (const float*)d_in[10];
    const float* gg      = (const float*)d_in[11];
    const float* bgg     = (const float*)d_in[12];
    const float* Wp      = (const float*)d_in[13];
    const float* bp      = (const float*)d_in[14];
    const float* gp      = (const float*)d_in[15];
    const float* bep     = (const float*)d_in[16];
    float* out = (float*)d_out;

    float *h, *tmp, *as_, *ad_;
    int *deg, *off, *cur, *csr;
    cudaGetSymbolAddress((void**)&h, g_h);
    cudaGetSymbolAddress((void**)&tmp, g_tmp);
    cudaGetSymbolAddress((void**)&as_, g_as);
    cudaGetSymbolAddress((void**)&ad_, g_ad);
    cudaGetSymbolAddress((void**)&deg, g_deg);
    cudaGetSymbolAddress((void**)&off, g_off);
    cudaGetSymbolAddress((void**)&cur, g_cur);
    cudaGetSymbolAddress((void**)&csr, g_csr_src);

    const int GEMM_SMEM = 4 * 128 * GSTR * sizeof(float);  // 139264 bytes
    cudaFuncSetAttribute(gemm_tf32_kernel, cudaFuncAttributeMaxDynamicSharedMemorySize,
                         GEMM_SMEM);
    const int GEMM_GRID = (NN + 127) / 128;

    // --- CSR by dst (built once per launch, reused by all layers) ---
    zero_deg_kernel<<<(NN + 255) / 256, 256>>>(deg);
    count_deg_kernel<<<(ET + 255) / 256, 256>>>(ei, deg);
    scan_kernel<<<1, 1024>>>(deg, off);
    copy_cursor_kernel<<<(NN + 255) / 256, 256>>>(off, cur);
    scatter_kernel<<<(ET + 255) / 256, 256>>>(ei, cur, csr);

    // --- node encoder ---
    gemm_tf32_kernel<<<GEMM_GRID, 256, GEMM_SMEM>>>(x, W0, tmp, NN);
    ln_silu_kernel<<<(NN * 32 + 255) / 256, 256>>>(tmp, b0, g0, be0, h);

    // --- 3 GAT layers ---
    for (int l = 0; l < LAYERS; l++) {
        gemm_tf32_kernel<<<GEMM_GRID, 256, GEMM_SMEM>>>(h, Wg + (long)l * 128 * 128, tmp, NN);
        attn_prep_kernel<<<(NN * HEADS + 255) / 256, 256>>>(
            tmp, att_src + l * 128, att_dst + l * 128, as_, ad_);
        gat_aggregate_kernel<<<(NN * 32 + 255) / 256, 256>>>(
            tmp, as_, ad_, off, csr, bg + l * 128, gg + l * 128, bgg + l * 128, h);
    }

    // --- fused global mean pool + output projection + LN + SiLU ---
    pool_final_kernel<<<NB, 128>>>(h, batch, Wp, bp, gp, bep, out);
}

// round 5
// speedup vs baseline: 1.3462x; 1.3462x over previous
#include <cuda_runtime.h>
#include <cuda_bf16.h>
#include <cstdint>

#define NN      50000
#define EE      800000
#define ET      850000
#define HID     128
#define HEADS   4
#define NB      64
#define LAYERS  3
#define LN_EPS  1e-5f
#define NEG_SLOPE 0.2f

// ---------------- device scratch ----------------
__device__ float g_h[NN * HID];
__device__ float g_tmp[NN * HID];
__device__ float g_as[NN * HEADS];
__device__ float g_ad[NN * HEADS];
__device__ int   g_deg[NN];
__device__ int   g_off[NN + 1];
__device__ int   g_cur[NN];
__device__ int   g_csr_src[ET];
__device__ __nv_bfloat16 g_wT_hi[4 * HID * HID];  // [w][n][k] = W[k][n] hi
__device__ __nv_bfloat16 g_wT_lo[4 * HID * HID];

// ---------------- helpers ----------------
__device__ __forceinline__ float warpSum(float v) {
#pragma unroll
    for (int o = 16; o > 0; o >>= 1) v += __shfl_xor_sync(0xffffffffu, v, o);
    return v;
}
__device__ __forceinline__ float lrelu(float x) { return x > 0.f ? x : NEG_SLOPE * x; }
__device__ __forceinline__ float silu(float x) { return x / (1.f + __expf(-x)); }

__device__ __forceinline__ void mma_bf16(float* c, const uint32_t* a, const uint32_t* b) {
    asm volatile(
        "mma.sync.aligned.m16n8k16.row.col.f32.bf16.bf16.f32 "
        "{%0,%1,%2,%3},{%4,%5,%6,%7},{%8,%9},{%0,%1,%2,%3};"
        : "+f"(c[0]), "+f"(c[1]), "+f"(c[2]), "+f"(c[3])
        : "r"(a[0]), "r"(a[1]), "r"(a[2]), "r"(a[3]), "r"(b[0]), "r"(b[1]));
}

__device__ __forceinline__ void split_pack(float a, float b, uint32_t& h, uint32_t& l) {
    __nv_bfloat16 ha = __float2bfloat16(a), hb = __float2bfloat16(b);
    __nv_bfloat162 hv = __halves2bfloat162(ha, hb);
    __nv_bfloat162 lv = __floats2bfloat162_rn(a - __bfloat162float(ha),
                                              b - __bfloat162float(hb));
    h = *(uint32_t*)&hv;
    l = *(uint32_t*)&lv;
}

// ---------------- weight prep: W^T split into bf16 hi/lo ----------------
__global__ void wprep_kernel(const float* __restrict__ W0, const float* __restrict__ Wg,
                             __nv_bfloat16* __restrict__ bh, __nv_bfloat16* __restrict__ bl) {
    int i = blockIdx.x * blockDim.x + threadIdx.x;
    if (i >= 4 * HID * HID) return;
    int w = i >> 14, rem = i & 16383, n = rem >> 7, k = rem & 127;
    const float* src = (w == 0) ? W0 : (Wg + (w - 1) * HID * HID);
    float v = src[k * HID + n];
    __nv_bfloat16 hi = __float2bfloat16(v);
    bh[i] = hi;
    bl[i] = __float2bfloat16(v - __bfloat162float(hi));
}

// ---------------- CSR build ----------------
__global__ void zero_deg_kernel(int* deg) {
    int i = blockIdx.x * blockDim.x + threadIdx.x;
    if (i < NN) deg[i] = 0;
}
__global__ void count_deg_kernel(const int* __restrict__ ei, int* __restrict__ deg) {
    int i = blockIdx.x * blockDim.x + threadIdx.x;
    if (i >= ET) return;
    int dst = (i < EE) ? ei[EE + i] : (i - EE);
    atomicAdd(&deg[dst], 1);
}
__global__ void scan_kernel(const int* __restrict__ deg, int* __restrict__ off) {
    __shared__ int wsum[32];
    __shared__ int carry;
    int tid = threadIdx.x, lane = tid & 31, w = tid >> 5;
    if (tid == 0) carry = 0;
    __syncthreads();
    for (int base = 0; base < NN; base += 1024) {
        int i = base + tid;
        int v = (i < NN) ? deg[i] : 0;
        int x = v;
#pragma unroll
        for (int o = 1; o < 32; o <<= 1) {
            int t = __shfl_up_sync(0xffffffffu, x, o);
            if (lane >= o) x += t;
        }
        if (lane == 31) wsum[w] = x;
        __syncthreads();
        if (w == 0) {
            int s = wsum[lane];
#pragma unroll
            for (int o = 1; o < 32; o <<= 1) {
                int t = __shfl_up_sync(0xffffffffu, s, o);
                if (lane >= o) s += t;
            }
            wsum[lane] = s;
        }
        __syncthreads();
        int excl = x - v + (w ? wsum[w - 1] : 0) + carry;
        if (i < NN) off[i] = excl;
        __syncthreads();
        if (tid == 0) carry += wsum[31];
        __syncthreads();
    }
    if (threadIdx.x == 0) off[NN] = carry;
}
__global__ void copy_cursor_kernel(const int* __restrict__ off, int* __restrict__ cur) {
    int i = blockIdx.x * blockDim.x + threadIdx.x;
    if (i < NN) cur[i] = off[i];
}
__global__ void scatter_kernel(const int* __restrict__ ei, int* __restrict__ cur,
                               int* __restrict__ csr_src) {
    int i = blockIdx.x * blockDim.x + threadIdx.x;
    if (i >= ET) return;
    int src, dst;
    if (i < EE) { src = ei[i]; dst = ei[EE + i]; }
    else        { src = i - EE; dst = i - EE; }
    int pos = atomicAdd(&cur[dst], 1);
    csr_src[pos] = src;
}

// ---------------- bf16 HMMA GEMM + fused epilogue ----------------
// C[M,128] = A[M,128] @ W[128,128], 3-term bf16 split (ah*bh + ah*bl + al*bh).
// mode 0: out = silu(layernorm(C + p0; p1, p2))
// mode 1: out = C;  a_s/a_d = per-head logits vs p0/p1
// smem row stride: 68 u32 (= 136 bf16 = 272 B) -> 64 u32 data + 4 pad.
#define U32STR 68
#define REGION (128 * U32STR * 4)          // 34816 B
#define SM_A_HI 0
#define SM_A_LO REGION
#define SM_B_HI (2 * REGION)
#define SM_B_LO (3 * REGION)
#define GEMM_SMEM (4 * REGION)             // 139264 B
#define CSTR 132                           // C smem stride in floats

__global__ __launch_bounds__(256, 1)
void gemm_tc_kernel(const float* __restrict__ A, const __nv_bfloat16* __restrict__ Bh,
                    const __nv_bfloat16* __restrict__ Bl, int M, int mode,
                    const float* __restrict__ p0, const float* __restrict__ p1,
                    const float* __restrict__ p2, float* __restrict__ out,
                    float* __restrict__ as_, float* __restrict__ ad_) {
    extern __shared__ char smem[];
    uint32_t* uAh = (uint32_t*)(smem + SM_A_HI);
    uint32_t* uAl = (uint32_t*)(smem + SM_A_LO);
    uint32_t* uBh = (uint32_t*)(smem + SM_B_HI);
    uint32_t* uBl = (uint32_t*)(smem + SM_B_LO);
    float* Cs = (float*)smem;

    const int tid = threadIdx.x, wid = tid >> 5, lane = tid & 31;
    const int g = lane >> 2, tig = lane & 3;
    const int rm = (wid >> 1) * 32;   // warp row base
    const int cn = (wid & 1) * 64;    // warp col base
    const int row0 = blockIdx.x * 128;

    // ---- load + split A (fp32 -> bf16 hi/lo): 4096 float4 groups, 16/thread
#pragma unroll
    for (int i = 0; i < 16; i++) {
        int idx = tid + i * 256;
        int r = idx >> 5;
        int c = (idx & 31) << 2;
        int gr = row0 + r;
        float4 v = make_float4(0.f, 0.f, 0.f, 0.f);
        if (gr < M) v = *(const float4*)(A + (long)gr * 128 + c);
        uint32_t h0, l0, h1, l1;
        split_pack(v.x, v.y, h0, l0);
        split_pack(v.z, v.w, h1, l1);
        int o = r * U32STR + (c >> 1);
        uAh[o] = h0; uAh[o + 1] = h1;
        uAl[o] = l0; uAl[o + 1] = l1;
    }
    // ---- load pre-split B [n][k]: 2048 uint4 groups, 8/thread
    const uint4* bhu = (const uint4*)Bh;
    const uint4* blu = (const uint4*)Bl;
#pragma unroll
    for (int i = 0; i < 8; i++) {
        int idx = tid + i * 256;
        int n = idx >> 4;
        int kg = (idx & 15) << 3;           // bf16 col within row
        int o = n * U32STR + (kg >> 1);     // u32 offset (16B aligned: kg>>1 % 4 == 0)
        *(uint4*)(uBh + o) = bhu[idx];
        *(uint4*)(uBl + o) = blu[idx];
    }
    __syncthreads();

    // ---- mma mainloop: 8 k-steps of 16
    float acc[2][8][4];
#pragma unroll
    for (int i = 0; i < 2; i++)
#pragma unroll
        for (int j = 0; j < 8; j++)
#pragma unroll
            for (int k = 0; k < 4; k++) acc[i][j][k] = 0.f;

#pragma unroll
    for (int ks = 0; ks < 8; ks++) {
        const int k32 = ks * 8 + tig;       // u32 index within row
        uint32_t ah[2][4], al[2][4], bh[8][2], bl[8][2];
#pragma unroll
        for (int mf = 0; mf < 2; mf++) {
            int r = rm + mf * 16 + g;
            ah[mf][0] = uAh[r * U32STR + k32];
            ah[mf][1] = uAh[(r + 8) * U32STR + k32];
            ah[mf][2] = uAh[r * U32STR + k32 + 4];
            ah[mf][3] = uAh[(r + 8) * U32STR + k32 + 4];
            al[mf][0] = uAl[r * U32STR + k32];
            al[mf][1] = uAl[(r + 8) * U32STR + k32];
            al[mf][2] = uAl[r * U32STR + k32 + 4];
            al[mf][3] = uAl[(r + 8) * U32STR + k32 + 4];
        }
#pragma unroll
        for (int nf = 0; nf < 8; nf++) {
            int c = cn + nf * 8 + g;
            bh[nf][0] = uBh[c * U32STR + k32];
            bh[nf][1] = uBh[c * U32STR + k32 + 4];
            bl[nf][0] = uBl[c * U32STR + k32];
            bl[nf][1] = uBl[c * U32STR + k32 + 4];
        }
#pragma unroll
        for (int mf = 0; mf < 2; mf++)
#pragma unroll
            for (int nf = 0; nf < 8; nf++) {
                mma_bf16(acc[mf][nf], al[mf], bh[nf]);
                mma_bf16(acc[mf][nf], ah[mf], bl[nf]);
                mma_bf16(acc[mf][nf], ah[mf], bh[nf]);
            }
    }
    __syncthreads();   // done reading A/B smem; reuse as C tile

    // ---- write accumulators to smem C
#pragma unroll
    for (int mf = 0; mf < 2; mf++) {
        int r = rm + mf * 16 + g;
#pragma unroll
        for (int nf = 0; nf < 8; nf++) {
            int c = cn + nf * 8 + tig * 2;
            *(float2*)(Cs + r * CSTR + c) = make_float2(acc[mf][nf][0], acc[mf][nf][1]);
            *(float2*)(Cs + (r + 8) * CSTR + c) = make_float2(acc[mf][nf][2], acc[mf][nf][3]);
        }
    }
    __syncthreads();

    // ---- fused epilogue: warp w handles rows w*16 .. w*16+15
    const int col = lane * 4;
#pragma unroll 1
    for (int i = 0; i < 16; i++) {
        int r = wid * 16 + i;
        int gr = row0 + r;
        if (gr >= M) break;
        float4 v = *(const float4*)(Cs + r * CSTR + col);
        if (mode == 0) {
            float4 b4 = *(const float4*)(p0 + col);
            v.x += b4.x; v.y += b4.y; v.z += b4.z; v.w += b4.w;
            float mu = warpSum(v.x + v.y + v.z + v.w) * (1.f / 128.f);
            float dx = v.x - mu, dy = v.y - mu, dz = v.z - mu, dw = v.w - mu;
            float var = warpSum(dx * dx + dy * dy + dz * dz + dw * dw) * (1.f / 128.f);
            float rs = rsqrtf(var + LN_EPS);
            float4 gv = *(const float4*)(p1 + col);
            float4 bv = *(const float4*)(p2 + col);
            float y;
            y = dx * rs * gv.x + bv.x; v.x = silu(y);
            y = dy * rs * gv.y + bv.y; v.y = silu(y);
            y = dz * rs * gv.z + bv.z; v.z = silu(y);
            y = dw * rs * gv.w + bv.w; v.w = silu(y);
            *(float4*)(out + (long)gr * 128 + col) = v;
        } else {
            *(float4*)(out + (long)gr * 128 + col) = v;
            float4 w1 = *(const float4*)(p0 + col);
            float4 w2 = *(const float4*)(p1 + col);
            float sa = v.x * w1.x + v.y * w1.y + v.z * w1.z + v.w * w1.w;
            float sd = v.x * w2.x + v.y * w2.y + v.z * w2.z + v.w * w2.w;
            // reduce within 8-lane head groups
#pragma unroll
            for (int o = 4; o > 0; o >>= 1) {
                sa += __shfl_xor_sync(0xffffffffu, sa, o);
                sd += __shfl_xor_sync(0xffffffffu, sd, o);
            }
            float a0 = __shfl_sync(0xffffffffu, sa, 0);
            float a1 = __shfl_sync(0xffffffffu, sa, 8);
            float a2 = __shfl_sync(0xffffffffu, sa, 16);
            float a3 = __shfl_sync(0xffffffffu, sa, 24);
            float d0 = __shfl_sync(0xffffffffu, sd, 0);
            float d1 = __shfl_sync(0xffffffffu, sd, 8);
            float d2 = __shfl_sync(0xffffffffu, sd, 16);
            float d3 = __shfl_sync(0xffffffffu, sd, 24);
            if (lane == 0) {
                *(float4*)(as_ + gr * 4) = make_float4(a0, a1, a2, a3);
                *(float4*)(ad_ + gr * 4) = make_float4(d0, d1, d2, d3);
            }
        }
    }
}

// -------- GAT aggregate (online softmax) + LN + SiLU + residual -----------
__global__ void gat_aggregate_kernel(const float* __restrict__ hh, const float* __restrict__ a_s,
                                     const float* __restrict__ a_d, const int* __restrict__ off,
                                     const int* __restrict__ csr_src, const float* __restrict__ bg,
                                     const float* __restrict__ gg, const float* __restrict__ bgg,
                                     float* __restrict__ h) {
    int n = (blockIdx.x * blockDim.x + threadIdx.x) >> 5;
    if (n >= NN) return;
    int lane = threadIdx.x & 31;
    int beg = off[n], end = off[n + 1];

    float4 adv = *(const float4*)(a_d + n * 4);
    float m0 = -1e30f, m1 = -1e30f, m2 = -1e30f, m3 = -1e30f;
    float s0 = 0.f, s1 = 0.f, s2 = 0.f, s3 = 0.f;
    for (int j = beg + lane; j < end; j += 32) {
        int s = csr_src[j];
        float4 asv = *(const float4*)(a_s + s * 4);
        float e;
        e = lrelu(asv.x + adv.x);
        if (e > m0) { s0 = s0 * __expf(m0 - e) + 1.f; m0 = e; } else s0 += __expf(e - m0);
        e = lrelu(asv.y + adv.y);
        if (e > m1) { s1 = s1 * __expf(m1 - e) + 1.f; m1 = e; } else s1 += __expf(e - m1);
        e = lrelu(asv.z + adv.z);
        if (e > m2) { s2 = s2 * __expf(m2 - e) + 1.f; m2 = e; } else s2 += __expf(e - m2);
        e = lrelu(asv.w + adv.w);
        if (e > m3) { s3 = s3 * __expf(m3 - e) + 1.f; m3 = e; } else s3 += __expf(e - m3);
    }
#pragma unroll
    for (int o = 16; o > 0; o >>= 1) {
        float om, os, nm;
        om = __shfl_xor_sync(0xffffffffu, m0, o); os = __shfl_xor_sync(0xffffffffu, s0, o);
        nm = fmaxf(m0, om); s0 = s0 * __expf(m0 - nm) + os * __expf(om - nm); m0 = nm;
        om = __shfl_xor_sync(0xffffffffu, m1, o); os = __shfl_xor_sync(0xffffffffu, s1, o);
        nm = fmaxf(m1, om); s1 = s1 * __expf(m1 - nm) + os * __expf(om - nm); m1 = nm;
        om = __shfl_xor_sync(0xffffffffu, m2, o); os = __shfl_xor_sync(0xffffffffu, s2, o);
        nm = fmaxf(m2, om); s2 = s2 * __expf(m2 - nm) + os * __expf(om - nm); m2 = nm;
        om = __shfl_xor_sync(0xffffffffu, m3, o); os = __shfl_xor_sync(0xffffffffu, s3, o);
        nm = fmaxf(m3, om); s3 = s3 * __expf(m3 - nm) + os * __expf(om - nm); m3 = nm;
    }

    int hd = lane >> 3;
    float mh   = (hd == 0) ? m0 : (hd == 1) ? m1 : (hd == 2) ? m2 : m3;
    float adh  = (hd == 0) ? adv.x : (hd == 1) ? adv.y : (hd == 2) ? adv.z : adv.w;
    float invh = 1.f / ((hd == 0) ? s0 : (hd == 1) ? s1 : (hd == 2) ? s2 : s3);

    const int col = lane * 4;
    float4 acc = make_float4(0.f, 0.f, 0.f, 0.f);
    for (int j = beg; j < end; j++) {
        int s = csr_src[j];
        float w = __expf(lrelu(a_s[s * 4 + hd] + adh) - mh) * invh;
        float4 v = *(const float4*)(hh + (long)s * 128 + col);
        acc.x += v.x * w; acc.y += v.y * w; acc.z += v.z * w; acc.w += v.w * w;
    }
    float4 bgv = *(const float4*)(bg + col);
    acc.x += bgv.x; acc.y += bgv.y; acc.z += bgv.z; acc.w += bgv.w;
    float mu = warpSum(acc.x + acc.y + acc.z + acc.w) * (1.f / 128.f);
    float dx = acc.x - mu, dy = acc.y - mu, dz = acc.z - mu, dw = acc.w - mu;
    float var = warpSum(dx * dx + dy * dy + dz * dz + dw * dw) * (1.f / 128.f);
    float r = rsqrtf(var + LN_EPS);
    float4 gv  = *(const float4*)(gg + col);
    float4 bv  = *(const float4*)(bgg + col);
    float4 old = *(const float4*)(h + (long)n * 128 + col);
    float y;
    y = dx * r * gv.x + bv.x; acc.x = silu(y) + old.x;
    y = dy * r * gv.y + bv.y; acc.y = silu(y) + old.y;
    y = dz * r * gv.z + bv.z; acc.z = silu(y) + old.z;
    y = dw * r * gv.w + bv.w; acc.w = silu(y) + old.w;
    *(float4*)(h + (long)n * 128 + col) = acc;
}

// -------- fused pool (sorted batch) + projection + LN + SiLU ------------
__global__ void pool_final_kernel(const float* __restrict__ h, const int* __restrict__ batch,
                                  const float* __restrict__ Wp, const float* __restrict__ bp,
                                  const float* __restrict__ gp, const float* __restrict__ bep,
                                  float* __restrict__ out) {
    __shared__ float p[128];
    __shared__ float sh[4];
    __shared__ int bounds[2];
    int b = blockIdx.x, t = threadIdx.x;
    int lane = t & 31, w = t >> 5;
    if (t < 2) {
        int target = b + t;
        int lo = 0, hi = NN;
        while (lo < hi) {
            int mid = (lo + hi) >> 1;
            if (batch[mid] < target) lo = mid + 1; else hi = mid;
        }
        bounds[t] = lo;
    }
    __syncthreads();
    int lo = bounds[0], hi = bounds[1];
    float s = 0.f;
#pragma unroll 4
    for (int n = lo; n < hi; n++) s += h[(long)n * 128 + t];
    float c = (float)(hi - lo > 0 ? hi - lo : 1);
    p[t] = s / c;
    __syncthreads();
    float acc = bp[t];
#pragma unroll 8
    for (int k = 0; k < 128; k++) acc += p[k] * Wp[k * 128 + t];
    float v = warpSum(acc);
    if (lane == 0) sh[w] = v;
    __syncthreads();
    float mu = (sh[0] + sh[1] + sh[2] + sh[3]) * (1.f / 128.f);
    __syncthreads();
    float d = acc - mu;
    v = warpSum(d * d);
    if (lane == 0) sh[w] = v;
    __syncthreads();
    float var = (sh[0] + sh[1] + sh[2] + sh[3]) * (1.f / 128.f);
    float r = rsqrtf(var + LN_EPS);
    float y = d * r * gp[t] + bep[t];
    out[b * 128 + t] = silu(y);
}

// ---------------- launch ----------------
extern "C" void kernel_launch(void* const* d_in, const int* in_sizes, int n_in,
                              void* d_out, int out_size) {
    const float* x       = (const float*)d_in[0];
    const int*   ei      = (const int*)d_in[1];
    const int*   batch   = (const int*)d_in[2];
    const float* W0      = (const float*)d_in[3];
    const float* b0      = (const float*)d_in[4];
    const float* g0      = (const float*)d_in[5];
    const float* be0     = (const float*)d_in[6];
    const float* Wg      = (const float*)d_in[7];
    const float* att_src = (const float*)d_in[8];
    const float* att_dst = (const float*)d_in[9];
    const float* bg      = (const float*)d_in[10];
    const float* gg      = (const float*)d_in[11];
    const float* bgg     = (const float*)d_in[12];
    const float* Wp      = (const float*)d_in[13];
    const float* bp      = (const float*)d_in[14];
    const float* gp      = (const float*)d_in[15];
    const float* bep     = (const float*)d_in[16];
    float* out = (float*)d_out;

    float *h, *tmp, *as_, *ad_;
    int *deg, *off, *cur, *csr;
    __nv_bfloat16 *wh, *wl;
    cudaGetSymbolAddress((void**)&h, g_h);
    cudaGetSymbolAddress((void**)&tmp, g_tmp);
    cudaGetSymbolAddress((void**)&as_, g_as);
    cudaGetSymbolAddress((void**)&ad_, g_ad);
    cudaGetSymbolAddress((void**)&deg, g_deg);
    cudaGetSymbolAddress((void**)&off, g_off);
    cudaGetSymbolAddress((void**)&cur, g_cur);
    cudaGetSymbolAddress((void**)&csr, g_csr_src);
    cudaGetSymbolAddress((void**)&wh, g_wT_hi);
    cudaGetSymbolAddress((void**)&wl, g_wT_lo);

    cudaFuncSetAttribute(gemm_tc_kernel, cudaFuncAttributeMaxDynamicSharedMemorySize,
                         GEMM_SMEM);
    const int GEMM_GRID = (NN + 127) / 128;

    // order chosen so the 6th launch (ncu -s 5 -c 1) is the tensor GEMM
    wprep_kernel<<<(4 * HID * HID + 255) / 256, 256>>>(W0, Wg, wh, wl);       // 0
    zero_deg_kernel<<<(NN + 255) / 256, 256>>>(deg);                          // 1
    count_deg_kernel<<<(ET + 255) / 256, 256>>>(ei, deg);                     // 2
    scan_kernel<<<1, 1024>>>(deg, off);                                       // 3
    copy_cursor_kernel<<<(NN + 255) / 256, 256>>>(off, cur);                  // 4
    gemm_tc_kernel<<<GEMM_GRID, 256, GEMM_SMEM>>>(x, wh, wl, NN, 0,           // 5
                                                  b0, g0, be0, h, nullptr, nullptr);
    scatter_kernel<<<(ET + 255) / 256, 256>>>(ei, cur, csr);                  // 6

    for (int l = 0; l < LAYERS; l++) {
        gemm_tc_kernel<<<GEMM_GRID, 256, GEMM_SMEM>>>(
            h, wh + (l + 1) * HID * HID, wl + (l + 1) * HID * HID, NN, 1,
            att_src + l * 128, att_dst + l * 128, nullptr, tmp, as_, ad_);
        gat_aggregate_kernel<<<(NN * 32 + 255) / 256, 256>>>(
            tmp, as_, ad_, off, csr, bg + l * 128, gg + l * 128, bgg + l * 128, h);
    }

    pool_final_kernel<<<NB, 128>>>(h, batch, Wp, bp, gp, bep, out);
}

// round 6
// speedup vs baseline: 1.4496x; 1.0768x over previous
#include <cuda_runtime.h>
#include <cuda_bf16.h>
#include <cstdint>

#define NN      50000
#define EE      800000
#define ET      850000
#define HID     128
#define HEADS   4
#define NB      64
#define LAYERS  3
#define LN_EPS  1e-5f
#define NEG_SLOPE 0.2f

#define SCAN_BLK 256
#define NBLK ((NN + SCAN_BLK - 1) / SCAN_BLK)   // 196

// ---------------- device scratch ----------------
__device__ float g_h[NN * HID];
__device__ float g_tmp[NN * HID];
__device__ float g_as[NN * HEADS];
__device__ float g_ad[NN * HEADS];
__device__ int   g_deg[NN];
__device__ int   g_off[NN + 1];
__device__ int   g_cur[NN];
__device__ int   g_bsum[NBLK];
__device__ int   g_csr_src[ET];
__device__ __nv_bfloat16 g_wT_hi[4 * HID * HID];  // [w][n][k] = W[k][n] hi
__device__ __nv_bfloat16 g_wT_lo[4 * HID * HID];

// ---------------- helpers ----------------
__device__ __forceinline__ float warpSum(float v) {
#pragma unroll
    for (int o = 16; o > 0; o >>= 1) v += __shfl_xor_sync(0xffffffffu, v, o);
    return v;
}
__device__ __forceinline__ int warpSumI(int v) {
#pragma unroll
    for (int o = 16; o > 0; o >>= 1) v += __shfl_xor_sync(0xffffffffu, v, o);
    return v;
}
__device__ __forceinline__ int warpScanIncl(int x, int lane) {
#pragma unroll
    for (int o = 1; o < 32; o <<= 1) {
        int t = __shfl_up_sync(0xffffffffu, x, o);
        if (lane >= o) x += t;
    }
    return x;
}
__device__ __forceinline__ float lrelu(float x) { return x > 0.f ? x : NEG_SLOPE * x; }
__device__ __forceinline__ float silu(float x) { return x / (1.f + __expf(-x)); }

__device__ __forceinline__ void mma_bf16(float* c, const uint32_t* a, const uint32_t* b) {
    asm volatile(
        "mma.sync.aligned.m16n8k16.row.col.f32.bf16.bf16.f32 "
        "{%0,%1,%2,%3},{%4,%5,%6,%7},{%8,%9},{%0,%1,%2,%3};"
        : "+f"(c[0]), "+f"(c[1]), "+f"(c[2]), "+f"(c[3])
        : "r"(a[0]), "r"(a[1]), "r"(a[2]), "r"(a[3]), "r"(b[0]), "r"(b[1]));
}

__device__ __forceinline__ void split_pack(float a, float b, uint32_t& h, uint32_t& l) {
    __nv_bfloat16 ha = __float2bfloat16(a), hb = __float2bfloat16(b);
    __nv_bfloat162 hv = __halves2bfloat162(ha, hb);
    __nv_bfloat162 lv = __floats2bfloat162_rn(a - __bfloat162float(ha),
                                              b - __bfloat162float(hb));
    h = *(uint32_t*)&hv;
    l = *(uint32_t*)&lv;
}

// ---------------- weight prep: W^T split into bf16 hi/lo ----------------
__global__ void wprep_kernel(const float* __restrict__ W0, const float* __restrict__ Wg,
                             __nv_bfloat16* __restrict__ bh, __nv_bfloat16* __restrict__ bl) {
    int i = blockIdx.x * blockDim.x + threadIdx.x;
    if (i >= 4 * HID * HID) return;
    int w = i >> 14, rem = i & 16383, n = rem >> 7, k = rem & 127;
    const float* src = (w == 0) ? W0 : (Wg + (w - 1) * HID * HID);
    float v = src[k * HID + n];
    __nv_bfloat16 hi = __float2bfloat16(v);
    bh[i] = hi;
    bl[i] = __float2bfloat16(v - __bfloat162float(hi));
}

// ---------------- CSR build ----------------
__global__ void zero_deg_kernel(int* deg) {
    int i = blockIdx.x * blockDim.x + threadIdx.x;
    if (i < NN) deg[i] = 0;
}
__global__ void count_deg_kernel(const int* __restrict__ ei, int* __restrict__ deg) {
    int i = blockIdx.x * blockDim.x + threadIdx.x;
    if (i >= ET) return;
    int dst = (i < EE) ? ei[EE + i] : (i - EE);
    atomicAdd(&deg[dst], 1);
}

// hierarchical scan: (1) per-block sums
__global__ void scan_part_kernel(const int* __restrict__ deg, int* __restrict__ bsum) {
    __shared__ int sh[SCAN_BLK / 32];
    int tid = threadIdx.x, lane = tid & 31, w = tid >> 5;
    int i = blockIdx.x * SCAN_BLK + tid;
    int v = (i < NN) ? deg[i] : 0;
    int s = warpSumI(v);
    if (lane == 0) sh[w] = s;
    __syncthreads();
    if (w == 0) {
        int t = (lane < SCAN_BLK / 32) ? sh[lane] : 0;
        t = warpSumI(t);
        if (lane == 0) bsum[blockIdx.x] = t;
    }
}
// (2) exclusive scan of the 196 block sums (single block); writes off[NN]=total
__global__ void scan_top_kernel(int* __restrict__ bsum, int* __restrict__ off) {
    __shared__ int sh[8];
    int tid = threadIdx.x, lane = tid & 31, w = tid >> 5;
    int v = (tid < NBLK) ? bsum[tid] : 0;
    int x = warpScanIncl(v, lane);
    if (lane == 31) sh[w] = x;
    __syncthreads();
    if (w == 0) {
        int t = (lane < 8) ? sh[lane] : 0;
        t = warpScanIncl(t, lane);
        if (lane < 8) sh[lane] = t;
    }
    __syncthreads();
    int incl = x + (w ? sh[w - 1] : 0);
    if (tid < NBLK) bsum[tid] = incl - v;      // exclusive
    if (tid == NBLK - 1) off[NN] = incl;       // total
}
// (3) within-block exclusive scan + block offset; writes off and cur
__global__ void scan_add_kernel(const int* __restrict__ deg, const int* __restrict__ bsum,
                                int* __restrict__ off, int* __restrict__ cur) {
    __shared__ int sh[SCAN_BLK / 32];
    int tid = threadIdx.x, lane = tid & 31, w = tid >> 5;
    int i = blockIdx.x * SCAN_BLK + tid;
    int v = (i < NN) ? deg[i] : 0;
    int x = warpScanIncl(v, lane);
    if (lane == 31) sh[w] = x;
    __syncthreads();
    if (w == 0) {
        int t = (lane < SCAN_BLK / 32) ? sh[lane] : 0;
        t = warpScanIncl(t, lane);
        if (lane < SCAN_BLK / 32) sh[lane] = t;
    }
    __syncthreads();
    int excl = x - v + (w ? sh[w - 1] : 0) + bsum[blockIdx.x];
    if (i < NN) {
        off[i] = excl;
        cur[i] = excl;
    }
}

__global__ void scatter_kernel(const int* __restrict__ ei, int* __restrict__ cur,
                               int* __restrict__ csr_src) {
    int i = blockIdx.x * blockDim.x + threadIdx.x;
    if (i >= ET) return;
    int src, dst;
    if (i < EE) { src = ei[i]; dst = ei[EE + i]; }
    else        { src = i - EE; dst = i - EE; }
    int pos = atomicAdd(&cur[dst], 1);
    csr_src[pos] = src;
}

// ---------------- bf16 HMMA GEMM + fused epilogue ----------------
// C[M,128] = A[M,128] @ W[128,128], 3-term bf16 split (ah*bh + ah*bl + al*bh).
// mode 0: out = silu(layernorm(C + p0; p1, p2))
// mode 1: out = C;  a_s/a_d = per-head logits vs p0/p1
// smem row stride: 68 u32 (= 136 bf16 = 272 B) -> 64 u32 data + 4 pad.
#define U32STR 68
#define REGION (128 * U32STR * 4)          // 34816 B
#define SM_A_HI 0
#define SM_A_LO REGION
#define SM_B_HI (2 * REGION)
#define SM_B_LO (3 * REGION)
#define GEMM_SMEM (4 * REGION)             // 139264 B
#define CSTR 132                           // C smem stride in floats

__global__ __launch_bounds__(256, 1)
void gemm_tc_kernel(const float* __restrict__ A, const __nv_bfloat16* __restrict__ Bh,
                    const __nv_bfloat16* __restrict__ Bl, int M, int mode,
                    const float* __restrict__ p0, const float* __restrict__ p1,
                    const float* __restrict__ p2, float* __restrict__ out,
                    float* __restrict__ as_, float* __restrict__ ad_) {
    extern __shared__ char smem[];
    uint32_t* uAh = (uint32_t*)(smem + SM_A_HI);
    uint32_t* uAl = (uint32_t*)(smem + SM_A_LO);
    uint32_t* uBh = (uint32_t*)(smem + SM_B_HI);
    uint32_t* uBl = (uint32_t*)(smem + SM_B_LO);
    float* Cs = (float*)smem;

    const int tid = threadIdx.x, wid = tid >> 5, lane = tid & 31;
    const int g = lane >> 2, tig = lane & 3;
    const int rm = (wid >> 1) * 32;   // warp row base
    const int cn = (wid & 1) * 64;    // warp col base
    const int row0 = blockIdx.x * 128;

    // ---- load + split A (fp32 -> bf16 hi/lo): 4096 float4 groups, 16/thread
#pragma unroll
    for (int i = 0; i < 16; i++) {
        int idx = tid + i * 256;
        int r = idx >> 5;
        int c = (idx & 31) << 2;
        int gr = row0 + r;
        float4 v = make_float4(0.f, 0.f, 0.f, 0.f);
        if (gr < M) v = *(const float4*)(A + (long)gr * 128 + c);
        uint32_t h0, l0, h1, l1;
        split_pack(v.x, v.y, h0, l0);
        split_pack(v.z, v.w, h1, l1);
        int o = r * U32STR + (c >> 1);
        uAh[o] = h0; uAh[o + 1] = h1;
        uAl[o] = l0; uAl[o + 1] = l1;
    }
    // ---- load pre-split B [n][k]: 2048 uint4 groups, 8/thread
    const uint4* bhu = (const uint4*)Bh;
    const uint4* blu = (const uint4*)Bl;
#pragma unroll
    for (int i = 0; i < 8; i++) {
        int idx = tid + i * 256;
        int n = idx >> 4;
        int kg = (idx & 15) << 3;           // bf16 col within row
        int o = n * U32STR + (kg >> 1);     // u32 offset (16B aligned)
        *(uint4*)(uBh + o) = bhu[idx];
        *(uint4*)(uBl + o) = blu[idx];
    }
    __syncthreads();

    // ---- mma mainloop: 8 k-steps of 16
    float acc[2][8][4];
#pragma unroll
    for (int i = 0; i < 2; i++)
#pragma unroll
        for (int j = 0; j < 8; j++)
#pragma unroll
            for (int k = 0; k < 4; k++) acc[i][j][k] = 0.f;

#pragma unroll
    for (int ks = 0; ks < 8; ks++) {
        const int k32 = ks * 8 + tig;       // u32 index within row
        uint32_t ah[2][4], al[2][4], bh[8][2], bl[8][2];
#pragma unroll
        for (int mf = 0; mf < 2; mf++) {
            int r = rm + mf * 16 + g;
            ah[mf][0] = uAh[r * U32STR + k32];
            ah[mf][1] = uAh[(r + 8) * U32STR + k32];
            ah[mf][2] = uAh[r * U32STR + k32 + 4];
            ah[mf][3] = uAh[(r + 8) * U32STR + k32 + 4];
            al[mf][0] = uAl[r * U32STR + k32];
            al[mf][1] = uAl[(r + 8) * U32STR + k32];
            al[mf][2] = uAl[r * U32STR + k32 + 4];
            al[mf][3] = uAl[(r + 8) * U32STR + k32 + 4];
        }
#pragma unroll
        for (int nf = 0; nf < 8; nf++) {
            int c = cn + nf * 8 + g;
            bh[nf][0] = uBh[c * U32STR + k32];
            bh[nf][1] = uBh[c * U32STR + k32 + 4];
            bl[nf][0] = uBl[c * U32STR + k32];
            bl[nf][1] = uBl[c * U32STR + k32 + 4];
        }
#pragma unroll
        for (int mf = 0; mf < 2; mf++)
#pragma unroll
            for (int nf = 0; nf < 8; nf++) {
                mma_bf16(acc[mf][nf], al[mf], bh[nf]);
                mma_bf16(acc[mf][nf], ah[mf], bl[nf]);
                mma_bf16(acc[mf][nf], ah[mf], bh[nf]);
            }
    }
    __syncthreads();   // done reading A/B smem; reuse as C tile

    // ---- write accumulators to smem C
#pragma unroll
    for (int mf = 0; mf < 2; mf++) {
        int r = rm + mf * 16 + g;
#pragma unroll
        for (int nf = 0; nf < 8; nf++) {
            int c = cn + nf * 8 + tig * 2;
            *(float2*)(Cs + r * CSTR + c) = make_float2(acc[mf][nf][0], acc[mf][nf][1]);
            *(float2*)(Cs + (r + 8) * CSTR + c) = make_float2(acc[mf][nf][2], acc[mf][nf][3]);
        }
    }
    __syncthreads();

    // ---- fused epilogue: warp w handles rows w*16 .. w*16+15
    const int col = lane * 4;
#pragma unroll 1
    for (int i = 0; i < 16; i++) {
        int r = wid * 16 + i;
        int gr = row0 + r;
        if (gr >= M) break;
        float4 v = *(const float4*)(Cs + r * CSTR + col);
        if (mode == 0) {
            float4 b4 = *(const float4*)(p0 + col);
            v.x += b4.x; v.y += b4.y; v.z += b4.z; v.w += b4.w;
            float mu = warpSum(v.x + v.y + v.z + v.w) * (1.f / 128.f);
            float dx = v.x - mu, dy = v.y - mu, dz = v.z - mu, dw = v.w - mu;
            float var = warpSum(dx * dx + dy * dy + dz * dz + dw * dw) * (1.f / 128.f);
            float rs = rsqrtf(var + LN_EPS);
            float4 gv = *(const float4*)(p1 + col);
            float4 bv = *(const float4*)(p2 + col);
            float y;
            y = dx * rs * gv.x + bv.x; v.x = silu(y);
            y = dy * rs * gv.y + bv.y; v.y = silu(y);
            y = dz * rs * gv.z + bv.z; v.z = silu(y);
            y = dw * rs * gv.w + bv.w; v.w = silu(y);
            *(float4*)(out + (long)gr * 128 + col) = v;
        } else {
            *(float4*)(out + (long)gr * 128 + col) = v;
            float4 w1 = *(const float4*)(p0 + col);
            float4 w2 = *(const float4*)(p1 + col);
            float sa = v.x * w1.x + v.y * w1.y + v.z * w1.z + v.w * w1.w;
            float sd = v.x * w2.x + v.y * w2.y + v.z * w2.z + v.w * w2.w;
            // reduce within 8-lane head groups
#pragma unroll
            for (int o = 4; o > 0; o >>= 1) {
                sa += __shfl_xor_sync(0xffffffffu, sa, o);
                sd += __shfl_xor_sync(0xffffffffu, sd, o);
            }
            float a0 = __shfl_sync(0xffffffffu, sa, 0);
            float a1 = __shfl_sync(0xffffffffu, sa, 8);
            float a2 = __shfl_sync(0xffffffffu, sa, 16);
            float a3 = __shfl_sync(0xffffffffu, sa, 24);
            float d0 = __shfl_sync(0xffffffffu, sd, 0);
            float d1 = __shfl_sync(0xffffffffu, sd, 8);
            float d2 = __shfl_sync(0xffffffffu, sd, 16);
            float d3 = __shfl_sync(0xffffffffu, sd, 24);
            if (lane == 0) {
                *(float4*)(as_ + gr * 4) = make_float4(a0, a1, a2, a3);
                *(float4*)(ad_ + gr * 4) = make_float4(d0, d1, d2, d3);
            }
        }
    }
}

// -------- GAT aggregate (online softmax) + LN + SiLU + residual -----------
__global__ void gat_aggregate_kernel(const float* __restrict__ hh, const float* __restrict__ a_s,
                                     const float* __restrict__ a_d, const int* __restrict__ off,
                                     const int* __restrict__ csr_src, const float* __restrict__ bg,
                                     const float* __restrict__ gg, const float* __restrict__ bgg,
                                     float* __restrict__ h) {
    int n = (blockIdx.x * blockDim.x + threadIdx.x) >> 5;
    if (n >= NN) return;
    int lane = threadIdx.x & 31;
    int beg = off[n], end = off[n + 1];

    float4 adv = *(const float4*)(a_d + n * 4);
    float m0 = -1e30f, m1 = -1e30f, m2 = -1e30f, m3 = -1e30f;
    float s0 = 0.f, s1 = 0.f, s2 = 0.f, s3 = 0.f;
    for (int j = beg + lane; j < end; j += 32) {
        int s = csr_src[j];
        float4 asv = *(const float4*)(a_s + s * 4);
        float e;
        e = lrelu(asv.x + adv.x);
        if (e > m0) { s0 = s0 * __expf(m0 - e) + 1.f; m0 = e; } else s0 += __expf(e - m0);
        e = lrelu(asv.y + adv.y);
        if (e > m1) { s1 = s1 * __expf(m1 - e) + 1.f; m1 = e; } else s1 += __expf(e - m1);
        e = lrelu(asv.z + adv.z);
        if (e > m2) { s2 = s2 * __expf(m2 - e) + 1.f; m2 = e; } else s2 += __expf(e - m2);
        e = lrelu(asv.w + adv.w);
        if (e > m3) { s3 = s3 * __expf(m3 - e) + 1.f; m3 = e; } else s3 += __expf(e - m3);
    }
#pragma unroll
    for (int o = 16; o > 0; o >>= 1) {
        float om, os, nm;
        om = __shfl_xor_sync(0xffffffffu, m0, o); os = __shfl_xor_sync(0xffffffffu, s0, o);
        nm = fmaxf(m0, om); s0 = s0 * __expf(m0 - nm) + os * __expf(om - nm); m0 = nm;
        om = __shfl_xor_sync(0xffffffffu, m1, o); os = __shfl_xor_sync(0xffffffffu, s1, o);
        nm = fmaxf(m1, om); s1 = s1 * __expf(m1 - nm) + os * __expf(om - nm); m1 = nm;
        om = __shfl_xor_sync(0xffffffffu, m2, o); os = __shfl_xor_sync(0xffffffffu, s2, o);
        nm = fmaxf(m2, om); s2 = s2 * __expf(m2 - nm) + os * __expf(om - nm); m2 = nm;
        om = __shfl_xor_sync(0xffffffffu, m3, o); os = __shfl_xor_sync(0xffffffffu, s3, o);
        nm = fmaxf(m3, om); s3 = s3 * __expf(m3 - nm) + os * __expf(om - nm); m3 = nm;
    }

    int hd = lane >> 3;
    float mh   = (hd == 0) ? m0 : (hd == 1) ? m1 : (hd == 2) ? m2 : m3;
    float adh  = (hd == 0) ? adv.x : (hd == 1) ? adv.y : (hd == 2) ? adv.z : adv.w;
    float invh = 1.f / ((hd == 0) ? s0 : (hd == 1) ? s1 : (hd == 2) ? s2 : s3);

    const int col = lane * 4;
    float4 acc = make_float4(0.f, 0.f, 0.f, 0.f);
    for (int j = beg; j < end; j++) {
        int s = csr_src[j];
        float w = __expf(lrelu(a_s[s * 4 + hd] + adh) - mh) * invh;
        float4 v = *(const float4*)(hh + (long)s * 128 + col);
        acc.x += v.x * w; acc.y += v.y * w; acc.z += v.z * w; acc.w += v.w * w;
    }
    float4 bgv = *(const float4*)(bg + col);
    acc.x += bgv.x; acc.y += bgv.y; acc.z += bgv.z; acc.w += bgv.w;
    float mu = warpSum(acc.x + acc.y + acc.z + acc.w) * (1.f / 128.f);
    float dx = acc.x - mu, dy = acc.y - mu, dz = acc.z - mu, dw = acc.w - mu;
    float var = warpSum(dx * dx + dy * dy + dz * dz + dw * dw) * (1.f / 128.f);
    float r = rsqrtf(var + LN_EPS);
    float4 gv  = *(const float4*)(gg + col);
    float4 bv  = *(const float4*)(bgg + col);
    float4 old = *(const float4*)(h + (long)n * 128 + col);
    float y;
    y = dx * r * gv.x + bv.x; acc.x = silu(y) + old.x;
    y = dy * r * gv.y + bv.y; acc.y = silu(y) + old.y;
    y = dz * r * gv.z + bv.z; acc.z = silu(y) + old.z;
    y = dw * r * gv.w + bv.w; acc.w = silu(y) + old.w;
    *(float4*)(h + (long)n * 128 + col) = acc;
}

// -------- fused pool (sorted batch) + projection + LN + SiLU ------------
__global__ void pool_final_kernel(const float* __restrict__ h, const int* __restrict__ batch,
                                  const float* __restrict__ Wp, const float* __restrict__ bp,
                                  const float* __restrict__ gp, const float* __restrict__ bep,
                                  float* __restrict__ out) {
    __shared__ float p[128];
    __shared__ float sh[4];
    __shared__ int bounds[2];
    int b = blockIdx.x, t = threadIdx.x;
    int lane = t & 31, w = t >> 5;
    if (t < 2) {
        int target = b + t;
        int lo = 0, hi = NN;
        while (lo < hi) {
            int mid = (lo + hi) >> 1;
            if (batch[mid] < target) lo = mid + 1; else hi = mid;
        }
        bounds[t] = lo;
    }
    __syncthreads();
    int lo = bounds[0], hi = bounds[1];
    float s = 0.f;
#pragma unroll 4
    for (int n = lo; n < hi; n++) s += h[(long)n * 128 + t];
    float c = (float)(hi - lo > 0 ? hi - lo : 1);
    p[t] = s / c;
    __syncthreads();
    float acc = bp[t];
#pragma unroll 8
    for (int k = 0; k < 128; k++) acc += p[k] * Wp[k * 128 + t];
    float v = warpSum(acc);
    if (lane == 0) sh[w] = v;
    __syncthreads();
    float mu = (sh[0] + sh[1] + sh[2] + sh[3]) * (1.f / 128.f);
    __syncthreads();
    float d = acc - mu;
    v = warpSum(d * d);
    if (lane == 0) sh[w] = v;
    __syncthreads();
    float var = (sh[0] + sh[1] + sh[2] + sh[3]) * (1.f / 128.f);
    float r = rsqrtf(var + LN_EPS);
    float y = d * r * gp[t] + bep[t];
    out[b * 128 + t] = silu(y);
}

// ---------------- launch ----------------
extern "C" void kernel_launch(void* const* d_in, const int* in_sizes, int n_in,
                              void* d_out, int out_size) {
    const float* x       = (const float*)d_in[0];
    const int*   ei      = (const int*)d_in[1];
    const int*   batch   = (const int*)d_in[2];
    const float* W0      = (const float*)d_in[3];
    const float* b0      = (const float*)d_in[4];
    const float* g0      = (const float*)d_in[5];
    const float* be0     = (const float*)d_in[6];
    const float* Wg      = (const float*)d_in[7];
    const float* att_src = (const float*)d_in[8];
    const float* att_dst = (const float*)d_in[9];
    const float* bg      = (const float*)d_in[10];
    const float* gg      = (const float*)d_in[11];
    const float* bgg     = (const float*)d_in[12];
    const float* Wp      = (const float*)d_in[13];
    const float* bp      = (const float*)d_in[14];
    const float* gp      = (const float*)d_in[15];
    const float* bep     = (const float*)d_in[16];
    float* out = (float*)d_out;

    float *h, *tmp, *as_, *ad_;
    int *deg, *off, *cur, *csr, *bsum;
    __nv_bfloat16 *wh, *wl;
    cudaGetSymbolAddress((void**)&h, g_h);
    cudaGetSymbolAddress((void**)&tmp, g_tmp);
    cudaGetSymbolAddress((void**)&as_, g_as);
    cudaGetSymbolAddress((void**)&ad_, g_ad);
    cudaGetSymbolAddress((void**)&deg, g_deg);
    cudaGetSymbolAddress((void**)&off, g_off);
    cudaGetSymbolAddress((void**)&cur, g_cur);
    cudaGetSymbolAddress((void**)&csr, g_csr_src);
    cudaGetSymbolAddress((void**)&bsum, g_bsum);
    cudaGetSymbolAddress((void**)&wh, g_wT_hi);
    cudaGetSymbolAddress((void**)&wl, g_wT_lo);

    cudaFuncSetAttribute(gemm_tc_kernel, cudaFuncAttributeMaxDynamicSharedMemorySize,
                         GEMM_SMEM);
    const int GEMM_GRID = (NN + 127) / 128;

    // launch order: index 3 = encoder GEMM (ncu captured index 3 last round)
    wprep_kernel<<<(4 * HID * HID + 255) / 256, 256>>>(W0, Wg, wh, wl);       // 0
    zero_deg_kernel<<<(NN + 255) / 256, 256>>>(deg);                          // 1
    count_deg_kernel<<<(ET + 255) / 256, 256>>>(ei, deg);                     // 2
    gemm_tc_kernel<<<GEMM_GRID, 256, GEMM_SMEM>>>(x, wh, wl, NN, 0,           // 3
                                                  b0, g0, be0, h, nullptr, nullptr);
    scan_part_kernel<<<NBLK, SCAN_BLK>>>(deg, bsum);                          // 4
    scan_top_kernel<<<1, 256>>>(bsum, off);                                   // 5
    scan_add_kernel<<<NBLK, SCAN_BLK>>>(deg, bsum, off, cur);                 // 6
    scatter_kernel<<<(ET + 255) / 256, 256>>>(ei, cur, csr);                  // 7

    for (int l = 0; l < LAYERS; l++) {
        gemm_tc_kernel<<<GEMM_GRID, 256, GEMM_SMEM>>>(
            h, wh + (l + 1) * HID * HID, wl + (l + 1) * HID * HID, NN, 1,
            att_src + l * 128, att_dst + l * 128, nullptr, tmp, as_, ad_);
        gat_aggregate_kernel<<<(NN * 32 + 255) / 256, 256>>>(
            tmp, as_, ad_, off, csr, bg + l * 128, gg + l * 128, bgg + l * 128, h);
    }

    pool_final_kernel<<<NB, 128>>>(h, batch, Wp, bp, gp, bep, out);
}

// round 7
// speedup vs baseline: 1.7040x; 1.1755x over previous
#include <cuda_runtime.h>
#include <cuda_bf16.h>
#include <cstdint>

#define NN      50000
#define EE      800000
#define ET      850000
#define HID     128
#define HEADS   4
#define NB      64
#define LAYERS  3
#define LN_EPS  1e-5f
#define NEG_SLOPE 0.2f

#define SCAN_BLK 256
#define NBLK ((NN + SCAN_BLK - 1) / SCAN_BLK)   // 196

// ---------------- device scratch ----------------
__device__ float g_h[NN * HID];
__device__ float g_tmp[NN * HID];
__device__ float g_as[NN * HEADS];
__device__ float g_ad[NN * HEADS];
__device__ int   g_deg[NN];
__device__ int   g_off[NN + 1];
__device__ int   g_cur[NN];
__device__ int   g_bsum[NBLK];
__device__ int   g_csr_src[ET];
__device__ __nv_bfloat16 g_wT_hi[4 * HID * HID];  // [w][n][k] = W[k][n] hi
__device__ __nv_bfloat16 g_wT_lo[4 * HID * HID];

// ---------------- helpers ----------------
__device__ __forceinline__ float warpSum(float v) {
#pragma unroll
    for (int o = 16; o > 0; o >>= 1) v += __shfl_xor_sync(0xffffffffu, v, o);
    return v;
}
__device__ __forceinline__ int warpSumI(int v) {
#pragma unroll
    for (int o = 16; o > 0; o >>= 1) v += __shfl_xor_sync(0xffffffffu, v, o);
    return v;
}
__device__ __forceinline__ int warpScanIncl(int x, int lane) {
#pragma unroll
    for (int o = 1; o < 32; o <<= 1) {
        int t = __shfl_up_sync(0xffffffffu, x, o);
        if (lane >= o) x += t;
    }
    return x;
}
__device__ __forceinline__ float lrelu(float x) { return x > 0.f ? x : NEG_SLOPE * x; }
__device__ __forceinline__ float silu(float x) { return x / (1.f + __expf(-x)); }

__device__ __forceinline__ void mma_bf16(float* c, const uint32_t* a, const uint32_t* b) {
    asm volatile(
        "mma.sync.aligned.m16n8k16.row.col.f32.bf16.bf16.f32 "
        "{%0,%1,%2,%3},{%4,%5,%6,%7},{%8,%9},{%0,%1,%2,%3};"
        : "+f"(c[0]), "+f"(c[1]), "+f"(c[2]), "+f"(c[3])
        : "r"(a[0]), "r"(a[1]), "r"(a[2]), "r"(a[3]), "r"(b[0]), "r"(b[1]));
}

__device__ __forceinline__ void split_pack(float a, float b, uint32_t& h, uint32_t& l) {
    __nv_bfloat16 ha = __float2bfloat16(a), hb = __float2bfloat16(b);
    __nv_bfloat162 hv = __halves2bfloat162(ha, hb);
    __nv_bfloat162 lv = __floats2bfloat162_rn(a - __bfloat162float(ha),
                                              b - __bfloat162float(hb));
    h = *(uint32_t*)&hv;
    l = *(uint32_t*)&lv;
}

// ---------------- weight prep: W^T split into bf16 hi/lo ----------------
__global__ void wprep_kernel(const float* __restrict__ W0, const float* __restrict__ Wg,
                             __nv_bfloat16* __restrict__ bh, __nv_bfloat16* __restrict__ bl) {
    int i = blockIdx.x * blockDim.x + threadIdx.x;
    if (i >= 4 * HID * HID) return;
    int w = i >> 14, rem = i & 16383, n = rem >> 7, k = rem & 127;
    const float* src = (w == 0) ? W0 : (Wg + (w - 1) * HID * HID);
    float v = src[k * HID + n];
    __nv_bfloat16 hi = __float2bfloat16(v);
    bh[i] = hi;
    bl[i] = __float2bfloat16(v - __bfloat162float(hi));
}

// ---------------- CSR build ----------------
__global__ void zero_deg_kernel(int* deg) {
    int i = blockIdx.x * blockDim.x + threadIdx.x;
    if (i < NN) deg[i] = 0;
}
__global__ void count_deg_kernel(const int* __restrict__ ei, int* __restrict__ deg) {
    int i = blockIdx.x * blockDim.x + threadIdx.x;
    if (i >= ET) return;
    int dst = (i < EE) ? ei[EE + i] : (i - EE);
    atomicAdd(&deg[dst], 1);
}

// hierarchical scan
__global__ void scan_part_kernel(const int* __restrict__ deg, int* __restrict__ bsum) {
    __shared__ int sh[SCAN_BLK / 32];
    int tid = threadIdx.x, lane = tid & 31, w = tid >> 5;
    int i = blockIdx.x * SCAN_BLK + tid;
    int v = (i < NN) ? deg[i] : 0;
    int s = warpSumI(v);
    if (lane == 0) sh[w] = s;
    __syncthreads();
    if (w == 0) {
        int t = (lane < SCAN_BLK / 32) ? sh[lane] : 0;
        t = warpSumI(t);
        if (lane == 0) bsum[blockIdx.x] = t;
    }
}
__global__ void scan_top_kernel(int* __restrict__ bsum, int* __restrict__ off) {
    __shared__ int sh[8];
    int tid = threadIdx.x, lane = tid & 31, w = tid >> 5;
    int v = (tid < NBLK) ? bsum[tid] : 0;
    int x = warpScanIncl(v, lane);
    if (lane == 31) sh[w] = x;
    __syncthreads();
    if (w == 0) {
        int t = (lane < 8) ? sh[lane] : 0;
        t = warpScanIncl(t, lane);
        if (lane < 8) sh[lane] = t;
    }
    __syncthreads();
    int incl = x + (w ? sh[w - 1] : 0);
    if (tid < NBLK) bsum[tid] = incl - v;
    if (tid == NBLK - 1) off[NN] = incl;
}
__global__ void scan_add_kernel(const int* __restrict__ deg, const int* __restrict__ bsum,
                                int* __restrict__ off, int* __restrict__ cur) {
    __shared__ int sh[SCAN_BLK / 32];
    int tid = threadIdx.x, lane = tid & 31, w = tid >> 5;
    int i = blockIdx.x * SCAN_BLK + tid;
    int v = (i < NN) ? deg[i] : 0;
    int x = warpScanIncl(v, lane);
    if (lane == 31) sh[w] = x;
    __syncthreads();
    if (w == 0) {
        int t = (lane < SCAN_BLK / 32) ? sh[lane] : 0;
        t = warpScanIncl(t, lane);
        if (lane < SCAN_BLK / 32) sh[lane] = t;
    }
    __syncthreads();
    int excl = x - v + (w ? sh[w - 1] : 0) + bsum[blockIdx.x];
    if (i < NN) {
        off[i] = excl;
        cur[i] = excl;
    }
}

__global__ void scatter_kernel(const int* __restrict__ ei, int* __restrict__ cur,
                               int* __restrict__ csr_src) {
    int i = blockIdx.x * blockDim.x + threadIdx.x;
    if (i >= ET) return;
    int src, dst;
    if (i < EE) { src = ei[i]; dst = ei[EE + i]; }
    else        { src = i - EE; dst = i - EE; }
    int pos = atomicAdd(&cur[dst], 1);
    csr_src[pos] = src;
}

// ---------------- bf16 HMMA GEMM + fused epilogue (512 thr, 16 warps) -------
// C[M,128] = A[M,128] @ W[128,128], 3-term bf16 split (ah*bh + ah*bl + al*bh).
// mode 0: out = silu(layernorm(C + p0; p1, p2))
// mode 1: out = C;  a_s/a_d = per-head logits vs p0/p1
// smem row stride: 68 u32 (= 136 bf16 = 272 B) -> 64 u32 data + 4 pad.
#define U32STR 68
#define REGION (128 * U32STR * 4)          // 34816 B
#define SM_A_HI 0
#define SM_A_LO REGION
#define SM_B_HI (2 * REGION)
#define SM_B_LO (3 * REGION)
#define GEMM_SMEM (4 * REGION)             // 139264 B
#define CSTR 132                           // C smem stride in floats

__global__ __launch_bounds__(512, 1)
void gemm_tc_kernel(const float* __restrict__ A, const __nv_bfloat16* __restrict__ Bh,
                    const __nv_bfloat16* __restrict__ Bl, int M, int mode,
                    const float* __restrict__ p0, const float* __restrict__ p1,
                    const float* __restrict__ p2, float* __restrict__ out,
                    float* __restrict__ as_, float* __restrict__ ad_) {
    extern __shared__ char smem[];
    uint32_t* uAh = (uint32_t*)(smem + SM_A_HI);
    uint32_t* uAl = (uint32_t*)(smem + SM_A_LO);
    uint32_t* uBh = (uint32_t*)(smem + SM_B_HI);
    uint32_t* uBl = (uint32_t*)(smem + SM_B_LO);
    float* Cs = (float*)smem;

    const int tid = threadIdx.x, wid = tid >> 5, lane = tid & 31;
    const int g = lane >> 2, tig = lane & 3;
    const int rm = (wid >> 2) * 32;   // warp row base (4 m-warps)
    const int cn = (wid & 3) * 32;    // warp col base (4 n-warps)
    const int row0 = blockIdx.x * 128;

    // ---- load + split A (fp32 -> bf16 hi/lo): 4096 float4 groups, 8/thread
#pragma unroll
    for (int i = 0; i < 8; i++) {
        int idx = tid + i * 512;
        int r = idx >> 5;
        int c = (idx & 31) << 2;
        int gr = row0 + r;
        float4 v = make_float4(0.f, 0.f, 0.f, 0.f);
        if (gr < M) v = *(const float4*)(A + (long)gr * 128 + c);
        uint32_t h0, l0, h1, l1;
        split_pack(v.x, v.y, h0, l0);
        split_pack(v.z, v.w, h1, l1);
        int o = r * U32STR + (c >> 1);
        uAh[o] = h0; uAh[o + 1] = h1;
        uAl[o] = l0; uAl[o + 1] = l1;
    }
    // ---- load pre-split B [n][k]: 2048 uint4 groups, 4/thread
    const uint4* bhu = (const uint4*)Bh;
    const uint4* blu = (const uint4*)Bl;
#pragma unroll
    for (int i = 0; i < 4; i++) {
        int idx = tid + i * 512;
        int n = idx >> 4;
        int kg = (idx & 15) << 3;           // bf16 col within row
        int o = n * U32STR + (kg >> 1);     // u32 offset (16B aligned)
        *(uint4*)(uBh + o) = bhu[idx];
        *(uint4*)(uBl + o) = blu[idx];
    }
    __syncthreads();

    // ---- mma mainloop: 8 k-steps of 16; warp tile 32x32 (2 mf x 4 nf)
    float acc[2][4][4];
#pragma unroll
    for (int i = 0; i < 2; i++)
#pragma unroll
        for (int j = 0; j < 4; j++)
#pragma unroll
            for (int k = 0; k < 4; k++) acc[i][j][k] = 0.f;

#pragma unroll
    for (int ks = 0; ks < 8; ks++) {
        const int k32 = ks * 8 + tig;       // u32 index within row
        uint32_t ah[2][4], al[2][4], bh[4][2], bl[4][2];
#pragma unroll
        for (int mf = 0; mf < 2; mf++) {
            int r = rm + mf * 16 + g;
            ah[mf][0] = uAh[r * U32STR + k32];
            ah[mf][1] = uAh[(r + 8) * U32STR + k32];
            ah[mf][2] = uAh[r * U32STR + k32 + 4];
            ah[mf][3] = uAh[(r + 8) * U32STR + k32 + 4];
            al[mf][0] = uAl[r * U32STR + k32];
            al[mf][1] = uAl[(r + 8) * U32STR + k32];
            al[mf][2] = uAl[r * U32STR + k32 + 4];
            al[mf][3] = uAl[(r + 8) * U32STR + k32 + 4];
        }
#pragma unroll
        for (int nf = 0; nf < 4; nf++) {
            int c = cn + nf * 8 + g;
            bh[nf][0] = uBh[c * U32STR + k32];
            bh[nf][1] = uBh[c * U32STR + k32 + 4];
            bl[nf][0] = uBl[c * U32STR + k32];
            bl[nf][1] = uBl[c * U32STR + k32 + 4];
        }
#pragma unroll
        for (int mf = 0; mf < 2; mf++)
#pragma unroll
            for (int nf = 0; nf < 4; nf++) {
                mma_bf16(acc[mf][nf], al[mf], bh[nf]);
                mma_bf16(acc[mf][nf], ah[mf], bl[nf]);
                mma_bf16(acc[mf][nf], ah[mf], bh[nf]);
            }
    }
    __syncthreads();   // done reading A/B smem; reuse as C tile

    // ---- write accumulators to smem C
#pragma unroll
    for (int mf = 0; mf < 2; mf++) {
        int r = rm + mf * 16 + g;
#pragma unroll
        for (int nf = 0; nf < 4; nf++) {
            int c = cn + nf * 8 + tig * 2;
            *(float2*)(Cs + r * CSTR + c) = make_float2(acc[mf][nf][0], acc[mf][nf][1]);
            *(float2*)(Cs + (r + 8) * CSTR + c) = make_float2(acc[mf][nf][2], acc[mf][nf][3]);
        }
    }
    __syncthreads();

    // ---- fused epilogue: warp w handles rows w*8 .. w*8+7
    const int col = lane * 4;
#pragma unroll 1
    for (int i = 0; i < 8; i++) {
        int r = wid * 8 + i;
        int gr = row0 + r;
        if (gr >= M) break;
        float4 v = *(const float4*)(Cs + r * CSTR + col);
        if (mode == 0) {
            float4 b4 = *(const float4*)(p0 + col);
            v.x += b4.x; v.y += b4.y; v.z += b4.z; v.w += b4.w;
            float mu = warpSum(v.x + v.y + v.z + v.w) * (1.f / 128.f);
            float dx = v.x - mu, dy = v.y - mu, dz = v.z - mu, dw = v.w - mu;
            float var = warpSum(dx * dx + dy * dy + dz * dz + dw * dw) * (1.f / 128.f);
            float rs = rsqrtf(var + LN_EPS);
            float4 gv = *(const float4*)(p1 + col);
            float4 bv = *(const float4*)(p2 + col);
            float y;
            y = dx * rs * gv.x + bv.x; v.x = silu(y);
            y = dy * rs * gv.y + bv.y; v.y = silu(y);
            y = dz * rs * gv.z + bv.z; v.z = silu(y);
            y = dw * rs * gv.w + bv.w; v.w = silu(y);
            *(float4*)(out + (long)gr * 128 + col) = v;
        } else {
            *(float4*)(out + (long)gr * 128 + col) = v;
            float4 w1 = *(const float4*)(p0 + col);
            float4 w2 = *(const float4*)(p1 + col);
            float sa = v.x * w1.x + v.y * w1.y + v.z * w1.z + v.w * w1.w;
            float sd = v.x * w2.x + v.y * w2.y + v.z * w2.z + v.w * w2.w;
#pragma unroll
            for (int o = 4; o > 0; o >>= 1) {
                sa += __shfl_xor_sync(0xffffffffu, sa, o);
                sd += __shfl_xor_sync(0xffffffffu, sd, o);
            }
            float a0 = __shfl_sync(0xffffffffu, sa, 0);
            float a1 = __shfl_sync(0xffffffffu, sa, 8);
            float a2 = __shfl_sync(0xffffffffu, sa, 16);
            float a3 = __shfl_sync(0xffffffffu, sa, 24);
            float d0 = __shfl_sync(0xffffffffu, sd, 0);
            float d1 = __shfl_sync(0xffffffffu, sd, 8);
            float d2 = __shfl_sync(0xffffffffu, sd, 16);
            float d3 = __shfl_sync(0xffffffffu, sd, 24);
            if (lane == 0) {
                *(float4*)(as_ + gr * 4) = make_float4(a0, a1, a2, a3);
                *(float4*)(ad_ + gr * 4) = make_float4(d0, d1, d2, d3);
            }
        }
    }
}

// -------- GAT aggregate (online softmax) + LN + SiLU + residual -----------
__global__ void gat_aggregate_kernel(const float* __restrict__ hh, const float* __restrict__ a_s,
                                     const float* __restrict__ a_d, const int* __restrict__ off,
                                     const int* __restrict__ csr_src, const float* __restrict__ bg,
                                     const float* __restrict__ gg, const float* __restrict__ bgg,
                                     float* __restrict__ h) {
    int n = (blockIdx.x * blockDim.x + threadIdx.x) >> 5;
    if (n >= NN) return;
    int lane = threadIdx.x & 31;
    int beg = off[n], end = off[n + 1];

    float4 adv = *(const float4*)(a_d + n * 4);
    float m0 = -1e30f, m1 = -1e30f, m2 = -1e30f, m3 = -1e30f;
    float s0 = 0.f, s1 = 0.f, s2 = 0.f, s3 = 0.f;
    for (int j = beg + lane; j < end; j += 32) {
        int s = csr_src[j];
        float4 asv = *(const float4*)(a_s + s * 4);
        float e;
        e = lrelu(asv.x + adv.x);
        if (e > m0) { s0 = s0 * __expf(m0 - e) + 1.f; m0 = e; } else s0 += __expf(e - m0);
        e = lrelu(asv.y + adv.y);
        if (e > m1) { s1 = s1 * __expf(m1 - e) + 1.f; m1 = e; } else s1 += __expf(e - m1);
        e = lrelu(asv.z + adv.z);
        if (e > m2) { s2 = s2 * __expf(m2 - e) + 1.f; m2 = e; } else s2 += __expf(e - m2);
        e = lrelu(asv.w + adv.w);
        if (e > m3) { s3 = s3 * __expf(m3 - e) + 1.f; m3 = e; } else s3 += __expf(e - m3);
    }
#pragma unroll
    for (int o = 16; o > 0; o >>= 1) {
        float om, os, nm;
        om = __shfl_xor_sync(0xffffffffu, m0, o); os = __shfl_xor_sync(0xffffffffu, s0, o);
        nm = fmaxf(m0, om); s0 = s0 * __expf(m0 - nm) + os * __expf(om - nm); m0 = nm;
        om = __shfl_xor_sync(0xffffffffu, m1, o); os = __shfl_xor_sync(0xffffffffu, s1, o);
        nm = fmaxf(m1, om); s1 = s1 * __expf(m1 - nm) + os * __expf(om - nm); m1 = nm;
        om = __shfl_xor_sync(0xffffffffu, m2, o); os = __shfl_xor_sync(0xffffffffu, s2, o);
        nm = fmaxf(m2, om); s2 = s2 * __expf(m2 - nm) + os * __expf(om - nm); m2 = nm;
        om = __shfl_xor_sync(0xffffffffu, m3, o); os = __shfl_xor_sync(0xffffffffu, s3, o);
        nm = fmaxf(m3, om); s3 = s3 * __expf(m3 - nm) + os * __expf(om - nm); m3 = nm;
    }

    int hd = lane >> 3;
    float mh   = (hd == 0) ? m0 : (hd == 1) ? m1 : (hd == 2) ? m2 : m3;
    float adh  = (hd == 0) ? adv.x : (hd == 1) ? adv.y : (hd == 2) ? adv.z : adv.w;
    float invh = 1.f / ((hd == 0) ? s0 : (hd == 1) ? s1 : (hd == 2) ? s2 : s3);

    const int col = lane * 4;
    float4 acc = make_float4(0.f, 0.f, 0.f, 0.f);
    for (int j = beg; j < end; j++) {
        int s = csr_src[j];
        float w = __expf(lrelu(a_s[s * 4 + hd] + adh) - mh) * invh;
        float4 v = *(const float4*)(hh + (long)s * 128 + col);
        acc.x += v.x * w; acc.y += v.y * w; acc.z += v.z * w; acc.w += v.w * w;
    }
    float4 bgv = *(const float4*)(bg + col);
    acc.x += bgv.x; acc.y += bgv.y; acc.z += bgv.z; acc.w += bgv.w;
    float mu = warpSum(acc.x + acc.y + acc.z + acc.w) * (1.f / 128.f);
    float dx = acc.x - mu, dy = acc.y - mu, dz = acc.z - mu, dw = acc.w - mu;
    float var = warpSum(dx * dx + dy * dy + dz * dz + dw * dw) * (1.f / 128.f);
    float r = rsqrtf(var + LN_EPS);
    float4 gv  = *(const float4*)(gg + col);
    float4 bv  = *(const float4*)(bgg + col);
    float4 old = *(const float4*)(h + (long)n * 128 + col);
    float y;
    y = dx * r * gv.x + bv.x; acc.x = silu(y) + old.x;
    y = dy * r * gv.y + bv.y; acc.y = silu(y) + old.y;
    y = dz * r * gv.z + bv.z; acc.z = silu(y) + old.z;
    y = dw * r * gv.w + bv.w; acc.w = silu(y) + old.w;
    *(float4*)(h + (long)n * 128 + col) = acc;
}

// -------- fused pool (sorted batch) + projection + LN + SiLU, 512 thr -----
__global__ __launch_bounds__(512)
void pool_final_kernel(const float* __restrict__ h, const int* __restrict__ batch,
                       const float* __restrict__ Wp, const float* __restrict__ bp,
                       const float* __restrict__ gp, const float* __restrict__ bep,
                       float* __restrict__ out) {
    __shared__ float part[4][128];
    __shared__ float p[128];
    __shared__ float accv[128];
    __shared__ float sh[4];
    __shared__ int bounds[2];
    int b = blockIdx.x, t = threadIdx.x;
    int col = t & 127, q = t >> 7;       // quarter 0..3
    int lane = t & 31;
    if (t < 2) {
        int target = b + t;
        int lo = 0, hi = NN;
        while (lo < hi) {
            int mid = (lo + hi) >> 1;
            if (batch[mid] < target) lo = mid + 1; else hi = mid;
        }
        bounds[t] = lo;
    }
    __syncthreads();
    int lo = bounds[0], hi = bounds[1];
    // 4-way row-split mean
    float s = 0.f;
    for (int n = lo + q; n < hi; n += 4) s += h[(long)n * 128 + col];
    part[q][col] = s;
    __syncthreads();
    if (t < 128) {
        float c = (float)(hi - lo > 0 ? hi - lo : 1);
        p[t] = (part[0][t] + part[1][t] + part[2][t] + part[3][t]) / c;
    }
    __syncthreads();
    // 4-way k-split projection
    float ap = 0.f;
#pragma unroll 8
    for (int k = q * 32; k < q * 32 + 32; k++) ap += p[k] * Wp[k * 128 + col];
    part[q][col] = ap;
    __syncthreads();
    if (t < 128) accv[t] = part[0][t] + part[1][t] + part[2][t] + part[3][t] + bp[t];
    __syncthreads();
    // LN over 128 values (all threads participate in barriers)
    float a = accv[col];
    float v = warpSum(a);
    if (t < 128 && lane == 0) sh[t >> 5] = v;
    __syncthreads();
    float mu = (sh[0] + sh[1] + sh[2] + sh[3]) * (1.f / 128.f);
    float d = a - mu;
    v = warpSum(d * d);
    __syncthreads();
    if (t < 128 && lane == 0) sh[t >> 5] = v;
    __syncthreads();
    float var = (sh[0] + sh[1] + sh[2] + sh[3]) * (1.f / 128.f);
    if (t < 128) {
        float r = rsqrtf(var + LN_EPS);
        float y = d * r * gp[t] + bep[t];
        out[b * 128 + t] = silu(y);
    }
}

// ---------------- launch ----------------
extern "C" void kernel_launch(void* const* d_in, const int* in_sizes, int n_in,
                              void* d_out, int out_size) {
    const float* x       = (const float*)d_in[0];
    const int*   ei      = (const int*)d_in[1];
    const int*   batch   = (const int*)d_in[2];
    const float* W0      = (const float*)d_in[3];
    const float* b0      = (const float*)d_in[4];
    const float* g0      = (const float*)d_in[5];
    const float* be0     = (const float*)d_in[6];
    const float* Wg      = (const float*)d_in[7];
    const float* att_src = (const float*)d_in[8];
    const float* att_dst = (const float*)d_in[9];
    const float* bg      = (const float*)d_in[10];
    const float* gg      = (const float*)d_in[11];
    const float* bgg     = (const float*)d_in[12];
    const float* Wp      = (const float*)d_in[13];
    const float* bp      = (const float*)d_in[14];
    const float* gp      = (const float*)d_in[15];
    const float* bep     = (const float*)d_in[16];
    float* out = (float*)d_out;

    float *h, *tmp, *as_, *ad_;
    int *deg, *off, *cur, *csr, *bsum;
    __nv_bfloat16 *wh, *wl;
    cudaGetSymbolAddress((void**)&h, g_h);
    cudaGetSymbolAddress((void**)&tmp, g_tmp);
    cudaGetSymbolAddress((void**)&as_, g_as);
    cudaGetSymbolAddress((void**)&ad_, g_ad);
    cudaGetSymbolAddress((void**)&deg, g_deg);
    cudaGetSymbolAddress((void**)&off, g_off);
    cudaGetSymbolAddress((void**)&cur, g_cur);
    cudaGetSymbolAddress((void**)&csr, g_csr_src);
    cudaGetSymbolAddress((void**)&bsum, g_bsum);
    cudaGetSymbolAddress((void**)&wh, g_wT_hi);
    cudaGetSymbolAddress((void**)&wl, g_wT_lo);

    cudaFuncSetAttribute(gemm_tc_kernel, cudaFuncAttributeMaxDynamicSharedMemorySize,
                         GEMM_SMEM);
    const int GEMM_GRID = (NN + 127) / 128;

    // launch order: index 3 = encoder GEMM (ncu captures the 4th launch)
    wprep_kernel<<<(4 * HID * HID + 255) / 256, 256>>>(W0, Wg, wh, wl);       // 0
    zero_deg_kernel<<<(NN + 255) / 256, 256>>>(deg);                          // 1
    count_deg_kernel<<<(ET + 255) / 256, 256>>>(ei, deg);                     // 2
    gemm_tc_kernel<<<GEMM_GRID, 512, GEMM_SMEM>>>(x, wh, wl, NN, 0,           // 3
                                                  b0, g0, be0, h, nullptr, nullptr);
    scan_part_kernel<<<NBLK, SCAN_BLK>>>(deg, bsum);                          // 4
    scan_top_kernel<<<1, 256>>>(bsum, off);                                   // 5
    scan_add_kernel<<<NBLK, SCAN_BLK>>>(deg, bsum, off, cur);                 // 6
    scatter_kernel<<<(ET + 255) / 256, 256>>>(ei, cur, csr);                  // 7

    for (int l = 0; l < LAYERS; l++) {
        gemm_tc_kernel<<<GEMM_GRID, 512, GEMM_SMEM>>>(
            h, wh + (l + 1) * HID * HID, wl + (l + 1) * HID * HID, NN, 1,
            att_src + l * 128, att_dst + l * 128, nullptr, tmp, as_, ad_);
        gat_aggregate_kernel<<<(NN * 32 + 255) / 256, 256>>>(
            tmp, as_, ad_, off, csr, bg + l * 128, gg + l * 128, bgg + l * 128, h);
    }

    pool_final_kernel<<<NB, 512>>>(h, batch, Wp, bp, gp, bep, out);
}